// round 2
// baseline (speedup 1.0000x reference)
#include <cuda_runtime.h>
#include <cuda_bf16.h>
#include <math.h>

// Problem constants
#define Bn   4
#define Cc   256
#define Hh   64
#define Ww   64
#define Pp   256
#define NK   9          // kernel points
#define PADc 6
#define DILc 6
#define Hp   76
#define Wp   76
#define Mpix (Bn*Hh*Ww)     // 16384
#define Kdim (Cc*NK)        // 2304

// ---------------- scratch (no allocations allowed) ----------------
__device__ float g_offmask[Bn * 27 * Hh * Ww];          // [b][ch 0..26][h][w]
__device__ float g_wt[Kdim * Pp];                       // Wt[K][o]
__device__ float g_cols[(size_t)Kdim * Mpix];           // cols[K][m], m = b*4096+h*64+w
__device__ float g_y[(size_t)Pp * Mpix];                // y[o][m]
__device__ float g_stats[2 * Pp];                       // mean[o], rstd[o]

// ---------------- kernel 1: fused offset(18) + mask(9) 3x3 conv, pad=1 ----------------
__global__ __launch_bounds__(256) void k_offmask_conv(
    const float* __restrict__ x, const float* __restrict__ w_p, const float* __restrict__ b_p,
    const float* __restrict__ w_m, const float* __restrict__ b_m)
{
    int oc = blockIdx.z % 27;
    int b  = blockIdx.z / 27;
    int h0 = blockIdx.y * 16, w0 = blockIdx.x * 16;

    __shared__ float tile[18 * 18];
    __shared__ float wsm[Cc * 9];

    int tx = threadIdx.x, ty = threadIdx.y;
    int tid = ty * 16 + tx;

    const float* wg = (oc < 18) ? (w_p + (size_t)oc * Cc * 9) : (w_m + (size_t)(oc - 18) * Cc * 9);
    float bias = (oc < 18) ? b_p[oc] : b_m[oc - 18];

    for (int i = tid; i < Cc * 9; i += 256) wsm[i] = wg[i];

    float acc = bias;
    const float* xb = x + (size_t)b * Cc * Hh * Ww;

    for (int c = 0; c < Cc; c++) {
        const float* xc = xb + (size_t)c * Hh * Ww;
        __syncthreads();
        for (int i = tid; i < 324; i += 256) {
            int r = i / 18, cc = i % 18;
            int hh = h0 + r - 1, ww = w0 + cc - 1;
            tile[i] = (hh >= 0 && hh < Hh && ww >= 0 && ww < Ww) ? xc[hh * Ww + ww] : 0.f;
        }
        __syncthreads();
        const float* wc = wsm + c * 9;
        #pragma unroll
        for (int kh = 0; kh < 3; kh++)
            #pragma unroll
            for (int kw = 0; kw < 3; kw++)
                acc = fmaf(tile[(ty + kh) * 18 + tx + kw], wc[kh * 3 + kw], acc);
    }
    g_offmask[((size_t)(b * 27 + oc) * 4096) + (h0 + ty) * Ww + (w0 + tx)] = acc;
}

// ---------------- kernel 2: transpose w[o][K] -> Wt[K][o] ----------------
__global__ __launch_bounds__(256) void k_transpose_w(const float* __restrict__ w)
{
    int i = blockIdx.x * 256 + threadIdx.x;           // over Pp*Kdim
    if (i < Pp * Kdim) {
        int o = i / Kdim;
        int k = i % Kdim;
        g_wt[(size_t)k * Pp + o] = w[i];
    }
}

// ---------------- kernel 3: deformable bilinear sampling -> cols[K][M] ----------------
// grid (h=64, k=9, b=4), block (w=64, cgroup=4)
__global__ __launch_bounds__(256) void k_sample(const float* __restrict__ x)
{
    int h = blockIdx.x, k = blockIdx.y, b = blockIdx.z;
    int w = threadIdx.x, cg = threadIdx.y;

    int base = ((b * 27) * Hh + h) * Ww + w;          // channel stride = 4096
    float offx  = g_offmask[base + k * 4096];
    float offy  = g_offmask[base + (9 + k) * 4096];
    float mlog  = g_offmask[base + (18 + k) * 4096];
    float mask  = 1.f / (1.f + expf(-mlog));

    int knh = k / 3, knw = k % 3;
    float px = (float)(h + 1) + (float)((knh - 1) * DILc) + offx;
    float py = (float)(w + 1) + (float)((knw - 1) * DILc) + offy;

    float flx = floorf(px), fly = floorf(py);
    float qltx = fminf(fmaxf(flx,        0.f), (float)(Hp - 1));
    float qlty = fminf(fmaxf(fly,        0.f), (float)(Wp - 1));
    float qrbx = fminf(fmaxf(flx + 1.f,  0.f), (float)(Hp - 1));
    float qrby = fminf(fmaxf(fly + 1.f,  0.f), (float)(Wp - 1));
    float pxc  = fminf(fmaxf(px, 0.f), (float)(Hp - 1));
    float pyc  = fminf(fmaxf(py, 0.f), (float)(Wp - 1));

    float glt = (1.f + (qltx - pxc)) * (1.f + (qlty - pyc)) * mask;
    float grb = (1.f - (qrbx - pxc)) * (1.f - (qrby - pyc)) * mask;
    float glb = (1.f + (qltx - pxc)) * (1.f - (qrby - pyc)) * mask;
    float grt = (1.f - (qrbx - pxc)) * (1.f + (qlty - pyc)) * mask;

    // padded coords -> unpadded coords
    int ltx = (int)qltx - PADc, lty = (int)qlty - PADc;
    int rbx = (int)qrbx - PADc, rby = (int)qrby - PADc;
    bool vltx = (unsigned)ltx < (unsigned)Hh, vlty = (unsigned)lty < (unsigned)Ww;
    bool vrbx = (unsigned)rbx < (unsigned)Hh, vrby = (unsigned)rby < (unsigned)Ww;

    int iLT = ltx * Ww + lty, iRB = rbx * Ww + rby;
    int iLB = ltx * Ww + rby, iRT = rbx * Ww + lty;
    bool bLT = vltx && vlty, bRB = vrbx && vrby;
    bool bLB = vltx && vrby, bRT = vrbx && vlty;

    const float* xb = x + (size_t)b * Cc * 4096;
    int m = (b * Hh + h) * Ww + w;

    for (int c = cg; c < Cc; c += 4) {
        const float* xc = xb + (size_t)c * 4096;
        float vlt = bLT ? __ldg(xc + iLT) : 0.f;
        float vrb = bRB ? __ldg(xc + iRB) : 0.f;
        float vlb = bLB ? __ldg(xc + iLB) : 0.f;
        float vrt = bRT ? __ldg(xc + iRT) : 0.f;
        g_cols[(size_t)(c * NK + k) * Mpix + m] =
            glt * vlt + grb * vrb + glb * vlb + grt * vrt;
    }
}

// ---------------- kernel 4: SGEMM  y[o][m] = sum_K Wt[K][o] * cols[K][m] ----------------
#define BM 128
#define BO 128
#define BKK 16
__global__ __launch_bounds__(256) void k_gemm()
{
    int m0 = blockIdx.x * BM;
    int o0 = blockIdx.y * BO;

    __shared__ float As[BKK][BM];   // cols tile  (k x m)
    __shared__ float Bs[BKK][BO];   // weight tile (k x o)

    int tid = threadIdx.x;
    int tm = tid % 16;   // m micro-tile
    int to = tid / 16;   // o micro-tile

    float acc[8][8];
    #pragma unroll
    for (int j = 0; j < 8; j++)
        #pragma unroll
        for (int i = 0; i < 8; i++) acc[j][i] = 0.f;

    for (int k0 = 0; k0 < Kdim; k0 += BKK) {
        #pragma unroll
        for (int ph = 0; ph < 2; ph++) {
            int idx = tid + ph * 256;            // 0..511 float4 units
            int row = idx >> 5;                  // 0..15
            int col = (idx & 31) << 2;           // 0..124
            float4 va = *(const float4*)&g_cols[(size_t)(k0 + row) * Mpix + m0 + col];
            *(float4*)&As[row][col] = va;
            float4 vb = *(const float4*)&g_wt[(size_t)(k0 + row) * Pp + o0 + col];
            *(float4*)&Bs[row][col] = vb;
        }
        __syncthreads();

        #pragma unroll
        for (int kk = 0; kk < BKK; kk++) {
            float a[8], bq[8];
            #pragma unroll
            for (int i = 0; i < 8; i++) a[i] = As[kk][tm * 8 + i];
            #pragma unroll
            for (int j = 0; j < 8; j++) bq[j] = Bs[kk][to * 8 + j];
            #pragma unroll
            for (int j = 0; j < 8; j++)
                #pragma unroll
                for (int i = 0; i < 8; i++)
                    acc[j][i] = fmaf(a[i], bq[j], acc[j][i]);
        }
        __syncthreads();
    }

    #pragma unroll
    for (int j = 0; j < 8; j++) {
        int o = o0 + to * 8 + j;
        float* dst = &g_y[(size_t)o * Mpix + m0 + tm * 8];
        *(float4*)&dst[0] = make_float4(acc[j][0], acc[j][1], acc[j][2], acc[j][3]);
        *(float4*)&dst[4] = make_float4(acc[j][4], acc[j][5], acc[j][6], acc[j][7]);
    }
}

// ---------------- kernel 5: BN statistics (one block per channel) ----------------
__global__ __launch_bounds__(256) void k_bnstats()
{
    int o = blockIdx.x, t = threadIdx.x;
    const float* yo = g_y + (size_t)o * Mpix;
    float s = 0.f, s2 = 0.f;
    for (int i = t; i < Mpix; i += 256) {
        float v = yo[i];
        s += v;
        s2 = fmaf(v, v, s2);
    }
    __shared__ float sh[2][8];
    #pragma unroll
    for (int off = 16; off; off >>= 1) {
        s  += __shfl_down_sync(0xFFFFFFFFu, s,  off);
        s2 += __shfl_down_sync(0xFFFFFFFFu, s2, off);
    }
    if ((t & 31) == 0) { sh[0][t >> 5] = s; sh[1][t >> 5] = s2; }
    __syncthreads();
    if (t < 32) {
        s  = (t < 8) ? sh[0][t] : 0.f;
        s2 = (t < 8) ? sh[1][t] : 0.f;
        #pragma unroll
        for (int off = 4; off; off >>= 1) {
            s  += __shfl_down_sync(0xFFFFFFFFu, s,  off);
            s2 += __shfl_down_sync(0xFFFFFFFFu, s2, off);
        }
        if (t == 0) {
            float mean = s * (1.f / (float)Mpix);
            float var  = s2 * (1.f / (float)Mpix) - mean * mean;
            g_stats[o]       = mean;
            g_stats[Pp + o]  = rsqrtf(var + 1e-5f);
        }
    }
}

// ---------------- kernel 6: BN apply + ReLU -> out[b][o][h][w] ----------------
__global__ __launch_bounds__(256) void k_bnapply(
    const float* __restrict__ gamma, const float* __restrict__ beta, float* __restrict__ out)
{
    int i = blockIdx.x * 256 + threadIdx.x;   // 0 .. 4194303
    int hw = i & 4095;
    int o  = (i >> 12) & 255;
    int b  = i >> 20;
    float v = g_y[(size_t)o * Mpix + b * 4096 + hw];
    float r = fmaf(gamma[o], (v - g_stats[o]) * g_stats[Pp + o], beta[o]);
    out[i] = fmaxf(r, 0.f);
}

// ---------------- launch ----------------
extern "C" void kernel_launch(void* const* d_in, const int* in_sizes, int n_in,
                              void* d_out, int out_size)
{
    const float* x     = (const float*)d_in[0];
    const float* w_p   = (const float*)d_in[1];
    const float* b_p   = (const float*)d_in[2];
    const float* w_m   = (const float*)d_in[3];
    const float* b_m   = (const float*)d_in[4];
    const float* w     = (const float*)d_in[5];
    const float* gamma = (const float*)d_in[6];
    const float* beta  = (const float*)d_in[7];
    float* out = (float*)d_out;

    k_offmask_conv<<<dim3(4, 4, Bn * 27), dim3(16, 16)>>>(x, w_p, b_p, w_m, b_m);
    k_transpose_w<<<(Pp * Kdim + 255) / 256, 256>>>(w);
    k_sample<<<dim3(Hh, NK, Bn), dim3(Ww, 4)>>>(x);
    k_gemm<<<dim3(Mpix / BM, Pp / BO), 256>>>();
    k_bnstats<<<Pp, 256>>>();
    k_bnapply<<<(Bn * Pp * Hh * Ww) / 256, 256>>>(gamma, beta, out);
}

// round 5
// speedup vs baseline: 2.7271x; 2.7271x over previous
#include <cuda_runtime.h>
#include <cuda_fp16.h>
#include <math.h>
#include <stdint.h>

// Problem constants
#define Bn   4
#define Cc   256
#define Hh   64
#define Ww   64
#define Pp   256
#define NK   9
#define PADc 6
#define DILc 6
#define Hp   76
#define Wp   76
#define Mpix (Bn*Hh*Ww)     // 16384
#define Kdim (Cc*NK)        // 2304
#define NIT  (Kdim/32)      // 72

// ---------------- scratch ----------------
__device__ float  g_offmask[Bn * 27 * Hh * Ww];                  // [b][ch0..26][h][w]
__device__ float  g_cpart[8 * 27 * Bn * Hh * Ww];                // conv partials
__device__ __half g_colh[(size_t)Kdim * Mpix];                   // A hi [k][m]
__device__ __half g_coll[(size_t)Kdim * Mpix];                   // A lo [k][m]
__device__ __half g_Bh[(size_t)NIT * Pp * 32];                   // B hi [kc][o][32]
__device__ __half g_Bl[(size_t)NIT * Pp * 32];                   // B lo
__device__ float  g_y[(size_t)Mpix * Pp];                        // y[m][o]
__device__ float  g_psum[128 * Pp];
__device__ float  g_psum2[128 * Pp];
__device__ float  g_scale[Pp];
__device__ float  g_shift[Pp];

#define SW128(off) ((off) ^ (((off) >> 3) & 0x70))

// ---------------- ptx helpers ----------------
__device__ __forceinline__ uint32_t smem_u32(const void* p) {
    uint32_t a;
    asm("{ .reg .u64 t; cvta.to.shared.u64 t, %1; cvt.u32.u64 %0, t; }" : "=r"(a) : "l"(p));
    return a;
}
__device__ __forceinline__ void cpasync16(uint32_t s, const void* g) {
    asm volatile("cp.async.cg.shared.global [%0], [%1], 16;" :: "r"(s), "l"(g));
}
__device__ __forceinline__ void cp_commit() {
    asm volatile("cp.async.commit_group;" ::: "memory");
}
template <int N> __device__ __forceinline__ void cp_wait() {
    asm volatile("cp.async.wait_group %0;" :: "n"(N) : "memory");
}
__device__ __forceinline__ void ldsm4t(uint32_t* r, uint32_t a) {
    asm volatile("ldmatrix.sync.aligned.m8n8.x4.trans.shared.b16 {%0,%1,%2,%3}, [%4];"
                 : "=r"(r[0]), "=r"(r[1]), "=r"(r[2]), "=r"(r[3]) : "r"(a));
}
__device__ __forceinline__ void ldsm4(uint32_t* r, uint32_t a) {
    asm volatile("ldmatrix.sync.aligned.m8n8.x4.shared.b16 {%0,%1,%2,%3}, [%4];"
                 : "=r"(r[0]), "=r"(r[1]), "=r"(r[2]), "=r"(r[3]) : "r"(a));
}
__device__ __forceinline__ void mma16816(float* c, const uint32_t* a, const uint32_t* b) {
    asm volatile("mma.sync.aligned.m16n8k16.row.col.f32.f16.f16.f32 "
                 "{%0,%1,%2,%3}, {%4,%5,%6,%7}, {%8,%9}, {%0,%1,%2,%3};"
                 : "+f"(c[0]), "+f"(c[1]), "+f"(c[2]), "+f"(c[3])
                 : "r"(a[0]), "r"(a[1]), "r"(a[2]), "r"(a[3]), "r"(b[0]), "r"(b[1]));
}

// ---------------- kernel 1: offset+mask conv, all 27 oc per block, 8-way channel split ----------------
__global__ __launch_bounds__(256) void k_conv27(
    const float* __restrict__ x, const float* __restrict__ w_p, const float* __restrict__ w_m)
{
    int z = blockIdx.z;            // b*8 + g
    int b = z >> 3, g = z & 7;
    int h0 = blockIdx.y * 16, w0 = blockIdx.x * 16;
    int tx = threadIdx.x, ty = threadIdx.y;
    int tid = ty * 16 + tx;

    __shared__ float tile[324];
    __shared__ float wsm[27 * 288];          // [oc][c(32)*9]

    for (int i = tid; i < 27 * 288; i += 256) {
        int oc = i / 288, rem = i % 288;
        wsm[i] = (oc < 18) ? w_p[(size_t)oc * Kdim + g * 288 + rem]
                           : w_m[(size_t)(oc - 18) * Kdim + g * 288 + rem];
    }

    float acc[27];
    #pragma unroll
    for (int oc = 0; oc < 27; oc++) acc[oc] = 0.f;

    const float* xb = x + (size_t)b * Cc * 4096;
    for (int c = 0; c < 32; c++) {
        const float* xc = xb + (size_t)(g * 32 + c) * 4096;
        __syncthreads();
        for (int i = tid; i < 324; i += 256) {
            int r = i / 18, cc = i % 18;
            int hh = h0 + r - 1, ww = w0 + cc - 1;
            tile[i] = (hh >= 0 && hh < Hh && ww >= 0 && ww < Ww) ? xc[hh * Ww + ww] : 0.f;
        }
        __syncthreads();
        float t[9];
        #pragma unroll
        for (int kh = 0; kh < 3; kh++)
            #pragma unroll
            for (int kw = 0; kw < 3; kw++)
                t[kh * 3 + kw] = tile[(ty + kh) * 18 + tx + kw];
        const float* wc = wsm + c * 9;
        #pragma unroll
        for (int oc = 0; oc < 27; oc++) {
            const float* wo = wc + oc * 288;
            #pragma unroll
            for (int j = 0; j < 9; j++)
                acc[oc] = fmaf(t[j], wo[j], acc[oc]);
        }
    }
    int pix = (h0 + ty) * Ww + w0 + tx;
    #pragma unroll
    for (int oc = 0; oc < 27; oc++)
        g_cpart[(size_t)g * (27 * Bn * 4096) + (size_t)(b * 27 + oc) * 4096 + pix] = acc[oc];
}

// ---------------- kernel 2: conv partial reduction + bias ----------------
__global__ __launch_bounds__(256) void k_convred(
    const float* __restrict__ b_p, const float* __restrict__ b_m)
{
    int i = blockIdx.x * 256 + threadIdx.x;     // 0..442367
    int oc = (i >> 12) % 27;
    float s = (oc < 18) ? b_p[oc] : b_m[oc - 18];
    #pragma unroll
    for (int g = 0; g < 8; g++)
        s += g_cpart[(size_t)g * (27 * Bn * 4096) + i];
    g_offmask[i] = s;
}

// ---------------- kernel 3: deformable sampling -> A hi/lo fp16 [k][m] ----------------
__global__ __launch_bounds__(256) void k_sample(const float* __restrict__ x)
{
    int h = blockIdx.x, k = blockIdx.y, b = blockIdx.z;
    int w = threadIdx.x, cg = threadIdx.y;

    int base = ((b * 27) * Hh + h) * Ww + w;
    float offx = g_offmask[base + k * 4096];
    float offy = g_offmask[base + (9 + k) * 4096];
    float mlog = g_offmask[base + (18 + k) * 4096];
    float mask = 1.f / (1.f + expf(-mlog));

    int knh = k / 3, knw = k % 3;
    float px = (float)(h + 1) + (float)((knh - 1) * DILc) + offx;
    float py = (float)(w + 1) + (float)((knw - 1) * DILc) + offy;

    float flx = floorf(px), fly = floorf(py);
    float qltx = fminf(fmaxf(flx,       0.f), (float)(Hp - 1));
    float qlty = fminf(fmaxf(fly,       0.f), (float)(Wp - 1));
    float qrbx = fminf(fmaxf(flx + 1.f, 0.f), (float)(Hp - 1));
    float qrby = fminf(fmaxf(fly + 1.f, 0.f), (float)(Wp - 1));
    float pxc  = fminf(fmaxf(px, 0.f), (float)(Hp - 1));
    float pyc  = fminf(fmaxf(py, 0.f), (float)(Wp - 1));

    float glt = (1.f + (qltx - pxc)) * (1.f + (qlty - pyc)) * mask;
    float grb = (1.f - (qrbx - pxc)) * (1.f - (qrby - pyc)) * mask;
    float glb = (1.f + (qltx - pxc)) * (1.f - (qrby - pyc)) * mask;
    float grt = (1.f - (qrbx - pxc)) * (1.f + (qlty - pyc)) * mask;

    int ltx = (int)qltx - PADc, lty = (int)qlty - PADc;
    int rbx = (int)qrbx - PADc, rby = (int)qrby - PADc;
    bool vltx = (unsigned)ltx < (unsigned)Hh, vlty = (unsigned)lty < (unsigned)Ww;
    bool vrbx = (unsigned)rbx < (unsigned)Hh, vrby = (unsigned)rby < (unsigned)Ww;

    int iLT = ltx * Ww + lty, iRB = rbx * Ww + rby;
    int iLB = ltx * Ww + rby, iRT = rbx * Ww + lty;
    bool bLT = vltx && vlty, bRB = vrbx && vrby;
    bool bLB = vltx && vrby, bRT = vrbx && vlty;

    const float* xb = x + (size_t)b * Cc * 4096;
    int m = (b * Hh + h) * Ww + w;

    for (int c = cg; c < Cc; c += 4) {
        const float* xc = xb + (size_t)c * 4096;
        float vlt = bLT ? __ldg(xc + iLT) : 0.f;
        float vrb = bRB ? __ldg(xc + iRB) : 0.f;
        float vlb = bLB ? __ldg(xc + iLB) : 0.f;
        float vrt = bRT ? __ldg(xc + iRT) : 0.f;
        float v = glt * vlt + grb * vrb + glb * vlb + grt * vrt;
        __half hi = __float2half_rn(v);
        float lo = v - __half2float(hi);
        size_t idx = (size_t)(c * NK + k) * Mpix + m;
        g_colh[idx] = hi;
        g_coll[idx] = __float2half_rn(lo);
    }
}

// ---------------- kernel 4: weight pack -> [kc][o][32] hi/lo fp16 ----------------
__global__ __launch_bounds__(256) void k_wpack(const float* __restrict__ w)
{
    int i = blockIdx.x * 256 + threadIdx.x;
    if (i < Pp * Kdim) {
        int o = i / Kdim, k = i % Kdim;
        float v = w[i];
        __half hi = __float2half_rn(v);
        float lo = v - __half2float(hi);
        size_t idx = (size_t)(k >> 5) * (Pp * 32) + o * 32 + (k & 31);
        g_Bh[idx] = hi;
        g_Bl[idx] = __float2half_rn(lo);
    }
}

// ---------------- kernel 5: HMMA GEMM  y[m][o] = A[m][:]*B[o][:], 3-pass hi/lo ----------------
// smem stage: A hi [0,8K) (2 halves of [k32][m64] SW128), A lo [8K,16K),
//             B hi [16K,32K) ([o256][k32] 64B rows, xor-swizzled), B lo [32K,48K)
#define STAGE 49152
#define GEMM_SMEM (2 * STAGE)

__device__ __forceinline__ void issue_tile(int kc, uint32_t sst, int tid, int m0)
{
    int k0 = kc * 32;
    #pragma unroll
    for (int p = 0; p < 2; p++) {
        int id = tid + p * 256;               // 0..511
        int kr = id >> 4, cm = id & 15;
        uint32_t so = (uint32_t)((cm >> 3) * 4096) + SW128((uint32_t)(kr * 128 + (cm & 7) * 16));
        const __half* gh = g_colh + (size_t)(k0 + kr) * Mpix + m0 + cm * 8;
        const __half* gl = g_coll + (size_t)(k0 + kr) * Mpix + m0 + cm * 8;
        cpasync16(sst + so, gh);
        cpasync16(sst + 8192 + so, gl);
    }
    #pragma unroll
    for (int p = 0; p < 4; p++) {
        int id = tid + p * 256;               // 0..1023
        int o = id >> 2, cc = id & 3;
        uint32_t so = (uint32_t)(o * 64 + ((cc ^ ((o >> 1) & 3)) << 4));
        const __half* gh = g_Bh + (size_t)kc * (Pp * 32) + o * 32 + cc * 8;
        const __half* gl = g_Bl + (size_t)kc * (Pp * 32) + o * 32 + cc * 8;
        cpasync16(sst + 16384 + so, gh);
        cpasync16(sst + 32768 + so, gl);
    }
}

__global__ __launch_bounds__(256, 1) void k_gemm_mma()
{
    extern __shared__ char smem[];
    uint32_t sb = smem_u32(smem);
    int tid = threadIdx.x;
    int lane = tid & 31, wid = tid >> 5;
    int wm = wid & 1, wn = wid >> 1;          // warp tile: 64m x 64n
    int m0 = blockIdx.x * 128;

    // ldmatrix lane address precompute
    int q = lane >> 3, r = lane & 7;
    int kb = (q >> 1) * 8, mb = (q & 1) * 8;
    int aoff[4];
    #pragma unroll
    for (int fm = 0; fm < 4; fm++) {
        int m = wm * 64 + fm * 16 + mb;
        int half = m >> 6, ml = m & 63, c = ml >> 3;
        aoff[fm] = half * 4096 + (kb + r) * 128 + ((c ^ r) << 4);
    }
    int bno[4], bsw[4];
    int cq = q & 1;
    #pragma unroll
    for (int g = 0; g < 4; g++) {
        int n = wn * 64 + g * 16 + ((q >> 1) & 1) * 8 + r;
        bno[g] = n * 64;
        bsw[g] = (n >> 1) & 3;
    }

    float acc[4][8][4];
    #pragma unroll
    for (int fm = 0; fm < 4; fm++)
        #pragma unroll
        for (int fn = 0; fn < 8; fn++)
            #pragma unroll
            for (int i = 0; i < 4; i++) acc[fm][fn][i] = 0.f;

    issue_tile(0, sb, tid, m0);
    cp_commit();

    for (int it = 0; it < NIT; it++) {
        if (it + 1 < NIT) {
            issue_tile(it + 1, sb + ((it + 1) & 1) * STAGE, tid, m0);
            cp_commit();
            cp_wait<1>();
        } else {
            cp_wait<0>();
        }
        __syncthreads();

        uint32_t abase = sb + (it & 1) * STAGE;
        uint32_t bbase = abase + 16384;

        #pragma unroll
        for (int ks = 0; ks < 2; ks++) {
            uint32_t ah[4][4], al[4][4], bq[4][4];
            #pragma unroll
            for (int fm = 0; fm < 4; fm++)
                ldsm4t(ah[fm], abase + aoff[fm] + ks * 2048);
            #pragma unroll
            for (int fm = 0; fm < 4; fm++)
                ldsm4t(al[fm], abase + 8192 + aoff[fm] + ks * 2048);
            #pragma unroll
            for (int g = 0; g < 4; g++)
                ldsm4(bq[g], bbase + bno[g] + (((ks * 2 + cq) ^ bsw[g]) << 4));
            // pass 1: Ah * Bh
            #pragma unroll
            for (int g = 0; g < 4; g++)
                #pragma unroll
                for (int h = 0; h < 2; h++)
                    #pragma unroll
                    for (int fm = 0; fm < 4; fm++)
                        mma16816(acc[fm][g * 2 + h], ah[fm], &bq[g][h * 2]);
            // pass 2: Al * Bh
            #pragma unroll
            for (int g = 0; g < 4; g++)
                #pragma unroll
                for (int h = 0; h < 2; h++)
                    #pragma unroll
                    for (int fm = 0; fm < 4; fm++)
                        mma16816(acc[fm][g * 2 + h], al[fm], &bq[g][h * 2]);
            // pass 3: Ah * Bl
            #pragma unroll
            for (int g = 0; g < 4; g++)
                ldsm4(bq[g], bbase + 16384 + bno[g] + (((ks * 2 + cq) ^ bsw[g]) << 4));
            #pragma unroll
            for (int g = 0; g < 4; g++)
                #pragma unroll
                for (int h = 0; h < 2; h++)
                    #pragma unroll
                    for (int fm = 0; fm < 4; fm++)
                        mma16816(acc[fm][g * 2 + h], ah[fm], &bq[g][h * 2]);
        }
        __syncthreads();
    }

    // epilogue -> g_y[m][o]
    int mrow = m0 + wm * 64 + (lane >> 2);
    int ocol = wn * 64 + (lane & 3) * 2;
    #pragma unroll
    for (int fm = 0; fm < 4; fm++) {
        int m = mrow + fm * 16;
        #pragma unroll
        for (int fn = 0; fn < 8; fn++) {
            int o = ocol + fn * 8;
            *(float2*)&g_y[(size_t)m * Pp + o]       = make_float2(acc[fm][fn][0], acc[fm][fn][1]);
            *(float2*)&g_y[(size_t)(m + 8) * Pp + o] = make_float2(acc[fm][fn][2], acc[fm][fn][3]);
        }
    }
}

// ---------------- kernel 6: BN partial stats (coalesced over y[m][o]) ----------------
__global__ __launch_bounds__(256) void k_bnstats()
{
    int bb = blockIdx.x, t = threadIdx.x;     // t = o
    float s = 0.f, s2 = 0.f;
    const float* yr = g_y + (size_t)bb * 128 * Pp + t;
    for (int i = 0; i < 128; i++) {
        float v = yr[(size_t)i * Pp];
        s += v;
        s2 = fmaf(v, v, s2);
    }
    g_psum[bb * Pp + t] = s;
    g_psum2[bb * Pp + t] = s2;
}

// ---------------- kernel 7: BN finalize ----------------
__global__ __launch_bounds__(256) void k_bnfin(
    const float* __restrict__ gamma, const float* __restrict__ beta)
{
    int o = threadIdx.x;
    float s = 0.f, s2 = 0.f;
    for (int b = 0; b < 128; b++) {
        s += g_psum[b * Pp + o];
        s2 += g_psum2[b * Pp + o];
    }
    float mean = s * (1.f / (float)Mpix);
    float var = s2 * (1.f / (float)Mpix) - mean * mean;
    float sc = gamma[o] * rsqrtf(var + 1e-5f);
    g_scale[o] = sc;
    g_shift[o] = beta[o] - mean * sc;
}

// ---------------- kernel 8: BN apply + ReLU, y[m][o] -> out[b][o][hw] (32x256 tile transpose) ----------------
__global__ __launch_bounds__(256) void k_bnapply(float* __restrict__ out)
{
    __shared__ float st[256][36];
    __shared__ float sc[256], sh[256];
    int t = threadIdx.x;
    int m0 = blockIdx.x * 32;
    sc[t] = g_scale[t];
    sh[t] = g_shift[t];
    __syncthreads();

    #pragma unroll
    for (int p = 0; p < 8; p++) {
        int idx = t + p * 256;                // 0..2047 float4 units
        int mi = idx >> 6, oc4 = idx & 63;
        float4 v = *(const float4*)&g_y[(size_t)(m0 + mi) * Pp + oc4 * 4];
        int o = oc4 * 4;
        st[o + 0][mi] = fmaxf(fmaf(v.x, sc[o + 0], sh[o + 0]), 0.f);
        st[o + 1][mi] = fmaxf(fmaf(v.y, sc[o + 1], sh[o + 1]), 0.f);
        st[o + 2][mi] = fmaxf(fmaf(v.z, sc[o + 2], sh[o + 2]), 0.f);
        st[o + 3][mi] = fmaxf(fmaf(v.w, sc[o + 3], sh[o + 3]), 0.f);
    }
    __syncthreads();

    int b = m0 >> 12;
    int hw0 = m0 & 4095;
    #pragma unroll
    for (int p = 0; p < 8; p++) {
        int idx = t + p * 256;                // 0..2047
        int o = idx >> 3, mq = idx & 7;
        float4 v = *(const float4*)&st[o][mq * 4];
        *(float4*)&out[(size_t)(b * 256 + o) * 4096 + hw0 + mq * 4] = v;
    }
}

// ---------------- launch ----------------
extern "C" void kernel_launch(void* const* d_in, const int* in_sizes, int n_in,
                              void* d_out, int out_size)
{
    const float* x     = (const float*)d_in[0];
    const float* w_p   = (const float*)d_in[1];
    const float* b_p   = (const float*)d_in[2];
    const float* w_m   = (const float*)d_in[3];
    const float* b_m   = (const float*)d_in[4];
    const float* w     = (const float*)d_in[5];
    const float* gamma = (const float*)d_in[6];
    const float* beta  = (const float*)d_in[7];
    float* out = (float*)d_out;

    cudaFuncSetAttribute(k_gemm_mma, cudaFuncAttributeMaxDynamicSharedMemorySize, GEMM_SMEM);

    k_conv27<<<dim3(4, 4, 32), dim3(16, 16)>>>(x, w_p, w_m);
    k_convred<<<1728, 256>>>(b_p, b_m);
    k_sample<<<dim3(Hh, NK, Bn), dim3(Ww, 4)>>>(x);
    k_wpack<<<(Pp * Kdim + 255) / 256, 256>>>(w);
    k_gemm_mma<<<Mpix / 128, 256, GEMM_SMEM>>>();
    k_bnstats<<<128, 256>>>();
    k_bnfin<<<1, 256>>>(gamma, beta);
    k_bnapply<<<Mpix / 32, 256>>>(out);
}

// round 6
// speedup vs baseline: 3.6206x; 1.3277x over previous
#include <cuda_runtime.h>
#include <cuda_fp16.h>
#include <math.h>
#include <stdint.h>

// Problem constants
#define Bn   4
#define Cc   256
#define Hh   64
#define Ww   64
#define Pp   256
#define NK   9
#define PADc 6
#define DILc 6
#define Hp   76
#define Wp   76
#define Mpix (Bn*Hh*Ww)     // 16384
#define Kdim (Cc*NK)        // 2304
#define NIT  (Kdim/32)      // 72

// ---------------- scratch ----------------
__device__ float  g_offmask[Bn * 27 * Hh * Ww];                  // [b][ch0..26][h][w]
__device__ __half g_xh[(size_t)Mpix * Cc];                       // xT hi [m][c]
__device__ __half g_xl[(size_t)Mpix * Cc];                       // xT lo
__device__ __half g_Wch[72 * 32 * 32];                           // conv W hi [it][o][c32]
__device__ __half g_Wcl[72 * 32 * 32];                           // conv W lo
__device__ __half g_colh[(size_t)Kdim * Mpix];                   // A hi [k][m]
__device__ __half g_coll[(size_t)Kdim * Mpix];                   // A lo [k][m]
__device__ __half g_Bh[(size_t)NIT * Pp * 32];                   // B hi [kc][o][32]
__device__ __half g_Bl[(size_t)NIT * Pp * 32];                   // B lo
__device__ float  g_y[(size_t)Mpix * Pp];                        // y[m][o]
__device__ float  g_psum[128 * Pp];
__device__ float  g_psum2[128 * Pp];
__device__ float  g_scale[Pp];
__device__ float  g_shift[Pp];

#define SW128(off) ((off) ^ (((off) >> 3) & 0x70))

// ---------------- ptx helpers ----------------
__device__ __forceinline__ uint32_t smem_u32(const void* p) {
    uint32_t a;
    asm("{ .reg .u64 t; cvta.to.shared.u64 t, %1; cvt.u32.u64 %0, t; }" : "=r"(a) : "l"(p));
    return a;
}
__device__ __forceinline__ void cpasync16(uint32_t s, const void* g) {
    asm volatile("cp.async.cg.shared.global [%0], [%1], 16;" :: "r"(s), "l"(g));
}
__device__ __forceinline__ void cpasync16z(uint32_t s, const void* g, uint32_t srcsz) {
    asm volatile("cp.async.cg.shared.global [%0], [%1], 16, %2;" :: "r"(s), "l"(g), "r"(srcsz));
}
__device__ __forceinline__ void cp_commit() {
    asm volatile("cp.async.commit_group;" ::: "memory");
}
template <int N> __device__ __forceinline__ void cp_wait() {
    asm volatile("cp.async.wait_group %0;" :: "n"(N) : "memory");
}
__device__ __forceinline__ void ldsm4t(uint32_t* r, uint32_t a) {
    asm volatile("ldmatrix.sync.aligned.m8n8.x4.trans.shared.b16 {%0,%1,%2,%3}, [%4];"
                 : "=r"(r[0]), "=r"(r[1]), "=r"(r[2]), "=r"(r[3]) : "r"(a));
}
__device__ __forceinline__ void ldsm4(uint32_t* r, uint32_t a) {
    asm volatile("ldmatrix.sync.aligned.m8n8.x4.shared.b16 {%0,%1,%2,%3}, [%4];"
                 : "=r"(r[0]), "=r"(r[1]), "=r"(r[2]), "=r"(r[3]) : "r"(a));
}
__device__ __forceinline__ void mma16816(float* c, const uint32_t* a, const uint32_t* b) {
    asm volatile("mma.sync.aligned.m16n8k16.row.col.f32.f16.f16.f32 "
                 "{%0,%1,%2,%3}, {%4,%5,%6,%7}, {%8,%9}, {%0,%1,%2,%3};"
                 : "+f"(c[0]), "+f"(c[1]), "+f"(c[2]), "+f"(c[3])
                 : "r"(a[0]), "r"(a[1]), "r"(a[2]), "r"(a[3]), "r"(b[0]), "r"(b[1]));
}

// ---------------- kernel 1: x transpose + fp16 split:  x[b][c][hw] -> xT[m][c] hi/lo ----------------
__global__ __launch_bounds__(256) void k_xsplit(const float* __restrict__ x)
{
    __shared__ float t[32][33];
    int hw0 = blockIdx.x * 32;
    int c0  = blockIdx.y * 32;
    int b   = blockIdx.z;
    int tx = threadIdx.x, ty = threadIdx.y;     // (32, 8)

    #pragma unroll
    for (int p = 0; p < 4; p++)
        t[ty + 8 * p][tx] = x[(size_t)(b * 256 + c0 + ty + 8 * p) * 4096 + hw0 + tx];
    __syncthreads();
    #pragma unroll
    for (int p = 0; p < 4; p++) {
        float v = t[tx][ty + 8 * p];            // x[c0+tx][hw0+ty+8p]
        __half hi = __float2half_rn(v);
        float lo = v - __half2float(hi);
        size_t idx = (size_t)(b * 4096 + hw0 + ty + 8 * p) * 256 + c0 + tx;
        g_xh[idx] = hi;
        g_xl[idx] = __float2half_rn(lo);
    }
}

// ---------------- kernel 2: conv weight pack [it=j*8+cc][o32][c32] hi/lo ----------------
__global__ __launch_bounds__(256) void k_wcpack(
    const float* __restrict__ w_p, const float* __restrict__ w_m)
{
    int i = blockIdx.x * 256 + threadIdx.x;     // 0..73727
    int it = i >> 10, o = (i >> 5) & 31, ci = i & 31;
    int j = it >> 3, cc = it & 7;
    int c = cc * 32 + ci;
    float v = 0.f;
    if (o < 18)      v = w_p[(size_t)o * Kdim + c * 9 + j];
    else if (o < 27) v = w_m[(size_t)(o - 18) * Kdim + c * 9 + j];
    __half hi = __float2half_rn(v);
    float lo = v - __half2float(hi);
    g_Wch[i] = hi;
    g_Wcl[i] = __float2half_rn(lo);
}

// ---------------- kernel 3: offset+mask conv as HMMA GEMM (9 shifted GEMMs over C) ----------------
// A[m][c] from xT shifted by delta(j), zero-filled rows for out-of-image taps.
// smem stage 20 KB: Ah[0,8K) (128m x 64B), Al[8K,16K), Bh[16K,18K) (32o x 64B), Bl[18K,20K)
__global__ __launch_bounds__(256, 2) void k_convmma(
    const float* __restrict__ b_p, const float* __restrict__ b_m)
{
    __shared__ char csm[2][20480];
    __shared__ float sbias[32];
    uint32_t sb0 = smem_u32(&csm[0][0]);
    int tid = threadIdx.x;
    int lane = tid & 31, wid = tid >> 5;
    int m0 = blockIdx.x * 128;

    if (tid < 32) sbias[tid] = (tid < 18) ? b_p[tid] : (tid < 27 ? b_m[tid - 18] : 0.f);

    int q = lane >> 3, r = lane & 7;

    // A frag address pieces (row = wm*16 + r + (q&1)*8, chunk ci = ks*2 + (q>>1))
    int arow = wid * 16 + r + (q & 1) * 8;
    int acix = q >> 1;
    uint32_t aso_base = (uint32_t)(arow * 64) ;
    int arsw = (arow >> 1) & 3;

    // B frag addresses: n = g*16 + ((q>>1)&1)*8 + r
    int bn[2], bsw[2];
    int cq = q & 1;
    #pragma unroll
    for (int g = 0; g < 2; g++) {
        int n = g * 16 + ((q >> 1) & 1) * 8 + r;
        bn[g] = n * 64;
        bsw[g] = (n >> 1) & 3;
    }

    float acc[4][4];   // fn(4 groups of 8 o) x 4
    #pragma unroll
    for (int fn = 0; fn < 4; fn++)
        #pragma unroll
        for (int i = 0; i < 4; i++) acc[fn][i] = 0.f;

    // producer lambda-ish: stage fill for iteration it (j = it>>3, cc = it&7)
    auto issue = [&](int it, int buf) {
        uint32_t sst = sb0 + buf * 20480;
        int j = it >> 3, cc = it & 7;
        int dh = j / 3 - 1, dw = j % 3 - 1;
        int delta = dh * 64 + dw;
        int c0 = cc * 32;
        #pragma unroll
        for (int p = 0; p < 4; p++) {
            int id = tid + p * 256;             // 0..1023
            int row = id >> 3, sub = id & 7;
            int half = sub >> 2, ci = sub & 3;
            int h = ((m0 + row) >> 6) & 63, w = row & 63;
            bool valid = ((unsigned)(h + dh) < 64u) && ((unsigned)(w + dw) < 64u);
            const __half* src = (half ? g_xl : g_xh);
            const __half* gp = valid ? (src + (size_t)(m0 + row + delta) * 256 + c0 + ci * 8)
                                     : src;
            uint32_t dst = sst + half * 8192 + row * 64 + ((ci ^ ((row >> 1) & 3)) << 4);
            cpasync16z(dst, gp, valid ? 16u : 0u);
        }
        // B: 32 o x 4 chunks x 2 (hi/lo) = 256 chunks, 1 per thread
        {
            int o = (tid >> 2) & 31, half = tid >> 7, ci = tid & 3;
            const __half* src = half ? g_Wcl : g_Wch;
            const __half* gp = src + ((size_t)it * 32 + o) * 32 + ci * 8;
            uint32_t dst = sst + 16384 + half * 2048 + o * 64 + ((ci ^ ((o >> 1) & 3)) << 4);
            cpasync16(dst, gp);
        }
    };

    issue(0, 0);
    cp_commit();

    for (int it = 0; it < 72; it++) {
        if (it + 1 < 72) {
            issue(it + 1, (it + 1) & 1);
            cp_commit();
            cp_wait<1>();
        } else {
            cp_wait<0>();
        }
        __syncthreads();

        uint32_t abase = sb0 + (it & 1) * 20480;
        uint32_t bbase = abase + 16384;

        #pragma unroll
        for (int ks = 0; ks < 2; ks++) {
            uint32_t ah[4], al[4], bq[2][4];
            {
                int ci = ks * 2 + acix;
                uint32_t so = aso_base + ((ci ^ arsw) << 4);
                ldsm4(ah, abase + so);
                ldsm4(al, abase + 8192 + so);
            }
            #pragma unroll
            for (int g = 0; g < 2; g++)
                ldsm4(bq[g], bbase + bn[g] + (((ks * 2 + cq) ^ bsw[g]) << 4));
            // pass1: Ah*Bh, pass2: Al*Bh
            #pragma unroll
            for (int g = 0; g < 2; g++)
                #pragma unroll
                for (int h = 0; h < 2; h++) {
                    mma16816(acc[g * 2 + h], ah, &bq[g][h * 2]);
                    mma16816(acc[g * 2 + h], al, &bq[g][h * 2]);
                }
            // pass3: Ah*Bl
            #pragma unroll
            for (int g = 0; g < 2; g++)
                ldsm4(bq[g], bbase + 2048 + bn[g] + (((ks * 2 + cq) ^ bsw[g]) << 4));
            #pragma unroll
            for (int g = 0; g < 2; g++)
                #pragma unroll
                for (int h = 0; h < 2; h++)
                    mma16816(acc[g * 2 + h], ah, &bq[g][h * 2]);
        }
        __syncthreads();
    }

    // epilogue: acc -> g_offmask[(b*27+o)*4096 + hw] + bias
    int mbase = m0 + wid * 16 + (lane >> 2);
    #pragma unroll
    for (int fn = 0; fn < 4; fn++) {
        #pragma unroll
        for (int hf = 0; hf < 2; hf++) {
            int m = mbase + hf * 8;
            int b = m >> 12, hw = m & 4095;
            #pragma unroll
            for (int e = 0; e < 2; e++) {
                int o = fn * 8 + (lane & 3) * 2 + e;
                if (o < 27)
                    g_offmask[(size_t)(b * 27 + o) * 4096 + hw] = acc[fn][hf * 2 + e] + sbias[o];
            }
        }
    }
}

// ---------------- kernel 4: deformable sampling -> A hi/lo fp16 [k][m] ----------------
__global__ __launch_bounds__(256) void k_sample(const float* __restrict__ x)
{
    int h = blockIdx.x, k = blockIdx.y, b = blockIdx.z;
    int w = threadIdx.x, cg = threadIdx.y;

    int base = ((b * 27) * Hh + h) * Ww + w;
    float offx = g_offmask[base + k * 4096];
    float offy = g_offmask[base + (9 + k) * 4096];
    float mlog = g_offmask[base + (18 + k) * 4096];
    float mask = 1.f / (1.f + expf(-mlog));

    int knh = k / 3, knw = k % 3;
    float px = (float)(h + 1) + (float)((knh - 1) * DILc) + offx;
    float py = (float)(w + 1) + (float)((knw - 1) * DILc) + offy;

    float flx = floorf(px), fly = floorf(py);
    float qltx = fminf(fmaxf(flx,       0.f), (float)(Hp - 1));
    float qlty = fminf(fmaxf(fly,       0.f), (float)(Wp - 1));
    float qrbx = fminf(fmaxf(flx + 1.f, 0.f), (float)(Hp - 1));
    float qrby = fminf(fmaxf(fly + 1.f, 0.f), (float)(Wp - 1));
    float pxc  = fminf(fmaxf(px, 0.f), (float)(Hp - 1));
    float pyc  = fminf(fmaxf(py, 0.f), (float)(Wp - 1));

    float glt = (1.f + (qltx - pxc)) * (1.f + (qlty - pyc)) * mask;
    float grb = (1.f - (qrbx - pxc)) * (1.f - (qrby - pyc)) * mask;
    float glb = (1.f + (qltx - pxc)) * (1.f - (qrby - pyc)) * mask;
    float grt = (1.f - (qrbx - pxc)) * (1.f + (qlty - pyc)) * mask;

    int ltx = (int)qltx - PADc, lty = (int)qlty - PADc;
    int rbx = (int)qrbx - PADc, rby = (int)qrby - PADc;
    bool vltx = (unsigned)ltx < (unsigned)Hh, vlty = (unsigned)lty < (unsigned)Ww;
    bool vrbx = (unsigned)rbx < (unsigned)Hh, vrby = (unsigned)rby < (unsigned)Ww;

    int iLT = ltx * Ww + lty, iRB = rbx * Ww + rby;
    int iLB = ltx * Ww + rby, iRT = rbx * Ww + lty;
    bool bLT = vltx && vlty, bRB = vrbx && vrby;
    bool bLB = vltx && vrby, bRT = vrbx && vlty;

    const float* xb = x + (size_t)b * Cc * 4096;
    int m = (b * Hh + h) * Ww + w;

    for (int c = cg; c < Cc; c += 4) {
        const float* xc = xb + (size_t)c * 4096;
        float vlt = bLT ? __ldg(xc + iLT) : 0.f;
        float vrb = bRB ? __ldg(xc + iRB) : 0.f;
        float vlb = bLB ? __ldg(xc + iLB) : 0.f;
        float vrt = bRT ? __ldg(xc + iRT) : 0.f;
        float v = glt * vlt + grb * vrb + glb * vlb + grt * vrt;
        __half hi = __float2half_rn(v);
        float lo = v - __half2float(hi);
        size_t idx = (size_t)(c * NK + k) * Mpix + m;
        g_colh[idx] = hi;
        g_coll[idx] = __float2half_rn(lo);
    }
}

// ---------------- kernel 5: main weight pack -> [kc][o][32] hi/lo fp16 ----------------
__global__ __launch_bounds__(256) void k_wpack(const float* __restrict__ w)
{
    int i = blockIdx.x * 256 + threadIdx.x;
    if (i < Pp * Kdim) {
        int o = i / Kdim, k = i % Kdim;
        float v = w[i];
        __half hi = __float2half_rn(v);
        float lo = v - __half2float(hi);
        size_t idx = (size_t)(k >> 5) * (Pp * 32) + o * 32 + (k & 31);
        g_Bh[idx] = hi;
        g_Bl[idx] = __float2half_rn(lo);
    }
}

// ---------------- kernel 6: main HMMA GEMM 128x128 tiles, 3-pass hi/lo ----------------
// stage 32 KB: Ah[0,8K) ([k32][m128] SW128 2 halves), Al[8K,16K),
//              Bh[16K,24K) ([o128][k32] 64B rows), Bl[24K,32K)
#define STAGE 32768
#define GEMM_SMEM (2 * STAGE)

__device__ __forceinline__ void issue_tile(int kc, uint32_t sst, int tid, int m0, int n0)
{
    int k0 = kc * 32;
    #pragma unroll
    for (int p = 0; p < 2; p++) {
        int id = tid + p * 256;               // 0..511
        int kr = id >> 4, cm = id & 15;
        uint32_t so = (uint32_t)((cm >> 3) * 4096) + SW128((uint32_t)(kr * 128 + (cm & 7) * 16));
        const __half* gh = g_colh + (size_t)(k0 + kr) * Mpix + m0 + cm * 8;
        const __half* gl = g_coll + (size_t)(k0 + kr) * Mpix + m0 + cm * 8;
        cpasync16(sst + so, gh);
        cpasync16(sst + 8192 + so, gl);
    }
    #pragma unroll
    for (int p = 0; p < 2; p++) {
        int id = tid + p * 256;               // 0..511
        int o = id >> 2, cc = id & 3;
        uint32_t so = (uint32_t)(o * 64 + ((cc ^ ((o >> 1) & 3)) << 4));
        const __half* gh = g_Bh + (size_t)kc * (Pp * 32) + (n0 + o) * 32 + cc * 8;
        const __half* gl = g_Bl + (size_t)kc * (Pp * 32) + (n0 + o) * 32 + cc * 8;
        cpasync16(sst + 16384 + so, gh);
        cpasync16(sst + 24576 + so, gl);
    }
}

__global__ __launch_bounds__(256, 2) void k_gemm_mma()
{
    extern __shared__ char smem[];
    uint32_t sb = smem_u32(smem);
    int tid = threadIdx.x;
    int lane = tid & 31, wid = tid >> 5;
    int wm = wid & 1, wn = wid >> 1;          // warp tile: 64m x 32n
    int m0 = blockIdx.x * 128;
    int n0 = blockIdx.y * 128;

    int q = lane >> 3, r = lane & 7;
    int kb = (q >> 1) * 8, mb = (q & 1) * 8;
    int aoff[4];
    #pragma unroll
    for (int fm = 0; fm < 4; fm++) {
        int m = wm * 64 + fm * 16 + mb;
        int half = m >> 6, ml = m & 63, c = ml >> 3;
        aoff[fm] = half * 4096 + (kb + r) * 128 + ((c ^ r) << 4);
    }
    int bno[2], bsw[2];
    int cq = q & 1;
    #pragma unroll
    for (int g = 0; g < 2; g++) {
        int n = wn * 32 + g * 16 + ((q >> 1) & 1) * 8 + r;
        bno[g] = n * 64;
        bsw[g] = (n >> 1) & 3;
    }

    float acc[4][4][4];
    #pragma unroll
    for (int fm = 0; fm < 4; fm++)
        #pragma unroll
        for (int fn = 0; fn < 4; fn++)
            #pragma unroll
            for (int i = 0; i < 4; i++) acc[fm][fn][i] = 0.f;

    issue_tile(0, sb, tid, m0, n0);
    cp_commit();

    for (int it = 0; it < NIT; it++) {
        if (it + 1 < NIT) {
            issue_tile(it + 1, sb + ((it + 1) & 1) * STAGE, tid, m0, n0);
            cp_commit();
            cp_wait<1>();
        } else {
            cp_wait<0>();
        }
        __syncthreads();

        uint32_t abase = sb + (it & 1) * STAGE;
        uint32_t bbase = abase + 16384;

        #pragma unroll
        for (int ks = 0; ks < 2; ks++) {
            uint32_t ah[4][4], al[4][4], bq[2][4];
            #pragma unroll
            for (int fm = 0; fm < 4; fm++)
                ldsm4t(ah[fm], abase + aoff[fm] + ks * 2048);
            #pragma unroll
            for (int fm = 0; fm < 4; fm++)
                ldsm4t(al[fm], abase + 8192 + aoff[fm] + ks * 2048);
            #pragma unroll
            for (int g = 0; g < 2; g++)
                ldsm4(bq[g], bbase + bno[g] + (((ks * 2 + cq) ^ bsw[g]) << 4));
            // pass1 Ah*Bh + pass2 Al*Bh
            #pragma unroll
            for (int g = 0; g < 2; g++)
                #pragma unroll
                for (int h = 0; h < 2; h++)
                    #pragma unroll
                    for (int fm = 0; fm < 4; fm++) {
                        mma16816(acc[fm][g * 2 + h], ah[fm], &bq[g][h * 2]);
                        mma16816(acc[fm][g * 2 + h], al[fm], &bq[g][h * 2]);
                    }
            // pass3 Ah*Bl
            #pragma unroll
            for (int g = 0; g < 2; g++)
                ldsm4(bq[g], bbase + 8192 + bno[g] + (((ks * 2 + cq) ^ bsw[g]) << 4));
            #pragma unroll
            for (int g = 0; g < 2; g++)
                #pragma unroll
                for (int h = 0; h < 2; h++)
                    #pragma unroll
                    for (int fm = 0; fm < 4; fm++)
                        mma16816(acc[fm][g * 2 + h], ah[fm], &bq[g][h * 2]);
        }
        __syncthreads();
    }

    // epilogue -> g_y[m][o]
    int mrow = m0 + wm * 64 + (lane >> 2);
    int ocol = n0 + wn * 32 + (lane & 3) * 2;
    #pragma unroll
    for (int fm = 0; fm < 4; fm++) {
        int m = mrow + fm * 16;
        #pragma unroll
        for (int fn = 0; fn < 4; fn++) {
            int o = ocol + fn * 8;
            *(float2*)&g_y[(size_t)m * Pp + o]       = make_float2(acc[fm][fn][0], acc[fm][fn][1]);
            *(float2*)&g_y[(size_t)(m + 8) * Pp + o] = make_float2(acc[fm][fn][2], acc[fm][fn][3]);
        }
    }
}

// ---------------- kernel 7: BN partial stats ----------------
__global__ __launch_bounds__(256) void k_bnstats()
{
    int bb = blockIdx.x, t = threadIdx.x;
    float s = 0.f, s2 = 0.f;
    const float* yr = g_y + (size_t)bb * 128 * Pp + t;
    for (int i = 0; i < 128; i++) {
        float v = yr[(size_t)i * Pp];
        s += v;
        s2 = fmaf(v, v, s2);
    }
    g_psum[bb * Pp + t] = s;
    g_psum2[bb * Pp + t] = s2;
}

// ---------------- kernel 8: BN finalize ----------------
__global__ __launch_bounds__(256) void k_bnfin(
    const float* __restrict__ gamma, const float* __restrict__ beta)
{
    int o = threadIdx.x;
    float s = 0.f, s2 = 0.f;
    for (int b = 0; b < 128; b++) {
        s += g_psum[b * Pp + o];
        s2 += g_psum2[b * Pp + o];
    }
    float mean = s * (1.f / (float)Mpix);
    float var = s2 * (1.f / (float)Mpix) - mean * mean;
    float sc = gamma[o] * rsqrtf(var + 1e-5f);
    g_scale[o] = sc;
    g_shift[o] = beta[o] - mean * sc;
}

// ---------------- kernel 9: BN apply + ReLU, y[m][o] -> out[b][o][hw] ----------------
__global__ __launch_bounds__(256) void k_bnapply(float* __restrict__ out)
{
    __shared__ float st[256][36];
    __shared__ float sc[256], sh[256];
    int t = threadIdx.x;
    int m0 = blockIdx.x * 32;
    sc[t] = g_scale[t];
    sh[t] = g_shift[t];
    __syncthreads();

    #pragma unroll
    for (int p = 0; p < 8; p++) {
        int idx = t + p * 256;
        int mi = idx >> 6, oc4 = idx & 63;
        float4 v = *(const float4*)&g_y[(size_t)(m0 + mi) * Pp + oc4 * 4];
        int o = oc4 * 4;
        st[o + 0][mi] = fmaxf(fmaf(v.x, sc[o + 0], sh[o + 0]), 0.f);
        st[o + 1][mi] = fmaxf(fmaf(v.y, sc[o + 1], sh[o + 1]), 0.f);
        st[o + 2][mi] = fmaxf(fmaf(v.z, sc[o + 2], sh[o + 2]), 0.f);
        st[o + 3][mi] = fmaxf(fmaf(v.w, sc[o + 3], sh[o + 3]), 0.f);
    }
    __syncthreads();

    int b = m0 >> 12;
    int hw0 = m0 & 4095;
    #pragma unroll
    for (int p = 0; p < 8; p++) {
        int idx = t + p * 256;
        int o = idx >> 3, mq = idx & 7;
        float4 v = *(const float4*)&st[o][mq * 4];
        *(float4*)&out[(size_t)(b * 256 + o) * 4096 + hw0 + mq * 4] = v;
    }
}

// ---------------- launch ----------------
extern "C" void kernel_launch(void* const* d_in, const int* in_sizes, int n_in,
                              void* d_out, int out_size)
{
    const float* x     = (const float*)d_in[0];
    const float* w_p   = (const float*)d_in[1];
    const float* b_p   = (const float*)d_in[2];
    const float* w_m   = (const float*)d_in[3];
    const float* b_m   = (const float*)d_in[4];
    const float* w     = (const float*)d_in[5];
    const float* gamma = (const float*)d_in[6];
    const float* beta  = (const float*)d_in[7];
    float* out = (float*)d_out;

    cudaFuncSetAttribute(k_gemm_mma, cudaFuncAttributeMaxDynamicSharedMemorySize, GEMM_SMEM);

    k_xsplit<<<dim3(128, 8, Bn), dim3(32, 8)>>>(x);
    k_wcpack<<<288, 256>>>(w_p, w_m);
    k_convmma<<<Mpix / 128, 256>>>(b_p, b_m);
    k_sample<<<dim3(Hh, NK, Bn), dim3(Ww, 4)>>>(x);
    k_wpack<<<(Pp * Kdim + 255) / 256, 256>>>(w);
    k_gemm_mma<<<dim3(Mpix / 128, 2), 256, GEMM_SMEM>>>();
    k_bnstats<<<128, 256>>>();
    k_bnfin<<<1, 256>>>(gamma, beta);
    k_bnapply<<<Mpix / 32, 256>>>(out);
}

// round 7
// speedup vs baseline: 4.3146x; 1.1917x over previous
#include <cuda_runtime.h>
#include <cuda_fp16.h>
#include <math.h>
#include <stdint.h>

// Problem constants
#define Bn   4
#define Cc   256
#define Hh   64
#define Ww   64
#define Pp   256
#define NK   9
#define PADc 6
#define DILc 6
#define Hp   76
#define Wp   76
#define Mpix (Bn*Hh*Ww)     // 16384
#define Kdim (Cc*NK)        // 2304
#define NIT  (Kdim/32)      // 72

// ---------------- scratch ----------------
__device__ float  g_offmask[Bn * 27 * Hh * Ww];                  // [b][ch0..26][h][w]
__device__ __half g_xh[(size_t)Mpix * Cc];                       // xT hi [m][c]
__device__ __half g_xl[(size_t)Mpix * Cc];                       // xT lo
__device__ __half g_Wch[72 * 32 * 32];                           // conv W hi [it][o][c32]
__device__ __half g_colh[(size_t)Kdim * Mpix];                   // A hi [k][m]
__device__ __half g_coll[(size_t)Kdim * Mpix];                   // A lo [k][m]
__device__ __half g_Bh[(size_t)NIT * Pp * 32];                   // B hi [kc][o][32]
__device__ float  g_y[(size_t)Mpix * Pp];                        // y[m][o]
__device__ float  g_psum[128 * Pp];
__device__ float  g_psum2[128 * Pp];
__device__ float  g_scale[Pp];
__device__ float  g_shift[Pp];

#define SW128(off) ((off) ^ (((off) >> 3) & 0x70))

// ---------------- ptx helpers ----------------
__device__ __forceinline__ uint32_t smem_u32(const void* p) {
    uint32_t a;
    asm("{ .reg .u64 t; cvta.to.shared.u64 t, %1; cvt.u32.u64 %0, t; }" : "=r"(a) : "l"(p));
    return a;
}
__device__ __forceinline__ void cpasync16(uint32_t s, const void* g) {
    asm volatile("cp.async.cg.shared.global [%0], [%1], 16;" :: "r"(s), "l"(g));
}
__device__ __forceinline__ void cpasync16z(uint32_t s, const void* g, uint32_t srcsz) {
    asm volatile("cp.async.cg.shared.global [%0], [%1], 16, %2;" :: "r"(s), "l"(g), "r"(srcsz));
}
__device__ __forceinline__ void cp_commit() {
    asm volatile("cp.async.commit_group;" ::: "memory");
}
template <int N> __device__ __forceinline__ void cp_wait() {
    asm volatile("cp.async.wait_group %0;" :: "n"(N) : "memory");
}
__device__ __forceinline__ void ldsm4t(uint32_t* r, uint32_t a) {
    asm volatile("ldmatrix.sync.aligned.m8n8.x4.trans.shared.b16 {%0,%1,%2,%3}, [%4];"
                 : "=r"(r[0]), "=r"(r[1]), "=r"(r[2]), "=r"(r[3]) : "r"(a));
}
__device__ __forceinline__ void ldsm4(uint32_t* r, uint32_t a) {
    asm volatile("ldmatrix.sync.aligned.m8n8.x4.shared.b16 {%0,%1,%2,%3}, [%4];"
                 : "=r"(r[0]), "=r"(r[1]), "=r"(r[2]), "=r"(r[3]) : "r"(a));
}
__device__ __forceinline__ void mma16816(float* c, const uint32_t* a, const uint32_t* b) {
    asm volatile("mma.sync.aligned.m16n8k16.row.col.f32.f16.f16.f32 "
                 "{%0,%1,%2,%3}, {%4,%5,%6,%7}, {%8,%9}, {%0,%1,%2,%3};"
                 : "+f"(c[0]), "+f"(c[1]), "+f"(c[2]), "+f"(c[3])
                 : "r"(a[0]), "r"(a[1]), "r"(a[2]), "r"(a[3]), "r"(b[0]), "r"(b[1]));
}

// ---------------- kernel 1: x transpose + fp16 split ----------------
__global__ __launch_bounds__(256) void k_xsplit(const float* __restrict__ x)
{
    __shared__ float t[32][33];
    int hw0 = blockIdx.x * 32;
    int c0  = blockIdx.y * 32;
    int b   = blockIdx.z;
    int tx = threadIdx.x, ty = threadIdx.y;

    #pragma unroll
    for (int p = 0; p < 4; p++)
        t[ty + 8 * p][tx] = x[(size_t)(b * 256 + c0 + ty + 8 * p) * 4096 + hw0 + tx];
    __syncthreads();
    #pragma unroll
    for (int p = 0; p < 4; p++) {
        float v = t[tx][ty + 8 * p];
        __half hi = __float2half_rn(v);
        float lo = v - __half2float(hi);
        size_t idx = (size_t)(b * 4096 + hw0 + ty + 8 * p) * 256 + c0 + tx;
        g_xh[idx] = hi;
        g_xl[idx] = __float2half_rn(lo);
    }
}

// ---------------- kernel 2: conv weight pack (hi only) ----------------
__global__ __launch_bounds__(256) void k_wcpack(
    const float* __restrict__ w_p, const float* __restrict__ w_m)
{
    int i = blockIdx.x * 256 + threadIdx.x;     // 0..73727
    int it = i >> 10, o = (i >> 5) & 31, ci = i & 31;
    int j = it >> 3, cc = it & 7;
    int c = cc * 32 + ci;
    float v = 0.f;
    if (o < 18)      v = w_p[(size_t)o * Kdim + c * 9 + j];
    else if (o < 27) v = w_m[(size_t)(o - 18) * Kdim + c * 9 + j];
    g_Wch[i] = __float2half_rn(v);
}

// ---------------- kernel 3: offset+mask conv as HMMA GEMM ----------------
// stage 18 KB: Ah[0,8K), Al[8K,16K), Bh[16K,18K)
#define CSTAGE 18432
__global__ __launch_bounds__(256, 2) void k_convmma(
    const float* __restrict__ b_p, const float* __restrict__ b_m)
{
    __shared__ char csm[2][CSTAGE];
    __shared__ float sbias[32];
    uint32_t sb0 = smem_u32(&csm[0][0]);
    int tid = threadIdx.x;
    int lane = tid & 31, wid = tid >> 5;
    int m0 = blockIdx.x * 128;

    if (tid < 32) sbias[tid] = (tid < 18) ? b_p[tid] : (tid < 27 ? b_m[tid - 18] : 0.f);

    int q = lane >> 3, r = lane & 7;
    int arow = wid * 16 + r + (q & 1) * 8;
    int acix = q >> 1;
    uint32_t aso_base = (uint32_t)(arow * 64);
    int arsw = (arow >> 1) & 3;

    int bn[2], bsw[2];
    int cq = q & 1;
    #pragma unroll
    for (int g = 0; g < 2; g++) {
        int n = g * 16 + ((q >> 1) & 1) * 8 + r;
        bn[g] = n * 64;
        bsw[g] = (n >> 1) & 3;
    }

    float acc[4][4];
    #pragma unroll
    for (int fn = 0; fn < 4; fn++)
        #pragma unroll
        for (int i = 0; i < 4; i++) acc[fn][i] = 0.f;

    auto issue = [&](int it, int buf) {
        uint32_t sst = sb0 + buf * CSTAGE;
        int j = it >> 3, cc = it & 7;
        int dh = j / 3 - 1, dw = j % 3 - 1;
        int delta = dh * 64 + dw;
        int c0 = cc * 32;
        #pragma unroll
        for (int p = 0; p < 4; p++) {
            int id = tid + p * 256;
            int row = id >> 3, sub = id & 7;
            int half = sub >> 2, ci = sub & 3;
            int h = ((m0 + row) >> 6) & 63, w = row & 63;
            bool valid = ((unsigned)(h + dh) < 64u) && ((unsigned)(w + dw) < 64u);
            const __half* src = (half ? g_xl : g_xh);
            const __half* gp = valid ? (src + (size_t)(m0 + row + delta) * 256 + c0 + ci * 8)
                                     : src;
            uint32_t dst = sst + half * 8192 + row * 64 + ((ci ^ ((row >> 1) & 3)) << 4);
            cpasync16z(dst, gp, valid ? 16u : 0u);
        }
        if (tid < 128) {
            int o = tid >> 2, ci = tid & 3;
            const __half* gp = g_Wch + ((size_t)it * 32 + o) * 32 + ci * 8;
            uint32_t dst = sst + 16384 + o * 64 + ((ci ^ ((o >> 1) & 3)) << 4);
            cpasync16(dst, gp);
        }
    };

    issue(0, 0);
    cp_commit();

    for (int it = 0; it < 72; it++) {
        if (it + 1 < 72) {
            issue(it + 1, (it + 1) & 1);
            cp_commit();
            cp_wait<1>();
        } else {
            cp_wait<0>();
        }
        __syncthreads();

        uint32_t abase = sb0 + (it & 1) * CSTAGE;
        uint32_t bbase = abase + 16384;

        #pragma unroll
        for (int ks = 0; ks < 2; ks++) {
            uint32_t ah[4], al[4], bq[2][4];
            {
                int ci = ks * 2 + acix;
                uint32_t so = aso_base + ((ci ^ arsw) << 4);
                ldsm4(ah, abase + so);
                ldsm4(al, abase + 8192 + so);
            }
            #pragma unroll
            for (int g = 0; g < 2; g++)
                ldsm4(bq[g], bbase + bn[g] + (((ks * 2 + cq) ^ bsw[g]) << 4));
            #pragma unroll
            for (int g = 0; g < 2; g++)
                #pragma unroll
                for (int h = 0; h < 2; h++) {
                    mma16816(acc[g * 2 + h], ah, &bq[g][h * 2]);
                    mma16816(acc[g * 2 + h], al, &bq[g][h * 2]);
                }
        }
        __syncthreads();
    }

    int mbase = m0 + wid * 16 + (lane >> 2);
    #pragma unroll
    for (int fn = 0; fn < 4; fn++) {
        #pragma unroll
        for (int hf = 0; hf < 2; hf++) {
            int m = mbase + hf * 8;
            int b = m >> 12, hw = m & 4095;
            #pragma unroll
            for (int e = 0; e < 2; e++) {
                int o = fn * 8 + (lane & 3) * 2 + e;
                if (o < 27)
                    g_offmask[(size_t)(b * 27 + o) * 4096 + hw] = acc[fn][hf * 2 + e] + sbias[o];
            }
        }
    }
}

// ---------------- kernel 4: deformable sampling, 2 pixels/thread ----------------
// grid (64, 9, 4), block (32, 8)
__global__ __launch_bounds__(256) void k_sample(const float* __restrict__ x)
{
    int h = blockIdx.x, k = blockIdx.y, b = blockIdx.z;
    int wp = threadIdx.x;       // pixel pair
    int cg = threadIdx.y;       // 0..7

    float wgt[2][4];
    int   idx[2][4];

    int knh = k / 3, knw = k % 3;

    #pragma unroll
    for (int e = 0; e < 2; e++) {
        int w = wp * 2 + e;
        int base = ((b * 27) * Hh + h) * Ww + w;
        float offx = g_offmask[base + k * 4096];
        float offy = g_offmask[base + (9 + k) * 4096];
        float mlog = g_offmask[base + (18 + k) * 4096];
        float mask = 1.f / (1.f + expf(-mlog));

        float px = (float)(h + 1) + (float)((knh - 1) * DILc) + offx;
        float py = (float)(w + 1) + (float)((knw - 1) * DILc) + offy;

        float flx = floorf(px), fly = floorf(py);
        float qltx = fminf(fmaxf(flx,       0.f), (float)(Hp - 1));
        float qlty = fminf(fmaxf(fly,       0.f), (float)(Wp - 1));
        float qrbx = fminf(fmaxf(flx + 1.f, 0.f), (float)(Hp - 1));
        float qrby = fminf(fmaxf(fly + 1.f, 0.f), (float)(Wp - 1));
        float pxc  = fminf(fmaxf(px, 0.f), (float)(Hp - 1));
        float pyc  = fminf(fmaxf(py, 0.f), (float)(Wp - 1));

        float glt = (1.f + (qltx - pxc)) * (1.f + (qlty - pyc)) * mask;
        float grb = (1.f - (qrbx - pxc)) * (1.f - (qrby - pyc)) * mask;
        float glb = (1.f + (qltx - pxc)) * (1.f - (qrby - pyc)) * mask;
        float grt = (1.f - (qrbx - pxc)) * (1.f + (qlty - pyc)) * mask;

        int ltx = (int)qltx - PADc, lty = (int)qlty - PADc;
        int rbx = (int)qrbx - PADc, rby = (int)qrby - PADc;
        bool vltx = (unsigned)ltx < (unsigned)Hh, vlty = (unsigned)lty < (unsigned)Ww;
        bool vrbx = (unsigned)rbx < (unsigned)Hh, vrby = (unsigned)rby < (unsigned)Ww;

        // fold validity into weights (invalid tap -> weight 0, index 0)
        bool bLT = vltx && vlty, bRB = vrbx && vrby;
        bool bLB = vltx && vrby, bRT = vrbx && vlty;
        wgt[e][0] = bLT ? glt : 0.f;  idx[e][0] = bLT ? (ltx * Ww + lty) : 0;
        wgt[e][1] = bRB ? grb : 0.f;  idx[e][1] = bRB ? (rbx * Ww + rby) : 0;
        wgt[e][2] = bLB ? glb : 0.f;  idx[e][2] = bLB ? (ltx * Ww + rby) : 0;
        wgt[e][3] = bRT ? grt : 0.f;  idx[e][3] = bRT ? (rbx * Ww + lty) : 0;
    }

    const float* xb = x + (size_t)b * Cc * 4096;
    int m = (b * Hh + h) * Ww + wp * 2;

    for (int c = cg; c < Cc; c += 8) {
        const float* xc = xb + (size_t)c * 4096;
        float v[2];
        #pragma unroll
        for (int e = 0; e < 2; e++) {
            v[e] = wgt[e][0] * __ldg(xc + idx[e][0])
                 + wgt[e][1] * __ldg(xc + idx[e][1])
                 + wgt[e][2] * __ldg(xc + idx[e][2])
                 + wgt[e][3] * __ldg(xc + idx[e][3]);
        }
        __half h0 = __float2half_rn(v[0]);
        __half h1 = __float2half_rn(v[1]);
        __half l0 = __float2half_rn(v[0] - __half2float(h0));
        __half l1 = __float2half_rn(v[1] - __half2float(h1));
        size_t base = (size_t)(c * NK + k) * Mpix + m;
        *(__half2*)&g_colh[base] = __halves2half2(h0, h1);
        *(__half2*)&g_coll[base] = __halves2half2(l0, l1);
    }
}

// ---------------- kernel 5: main weight pack (hi only) ----------------
__global__ __launch_bounds__(256) void k_wpack(const float* __restrict__ w)
{
    int i = blockIdx.x * 256 + threadIdx.x;
    if (i < Pp * Kdim) {
        int o = i / Kdim, k = i % Kdim;
        size_t idx = (size_t)(k >> 5) * (Pp * 32) + o * 32 + (k & 31);
        g_Bh[idx] = __float2half_rn(w[i]);
    }
}

// ---------------- kernel 6: main HMMA GEMM 128x128 tiles, 2-pass (Ah+Al)*Bh ----------------
// stage 24 KB: Ah[0,8K), Al[8K,16K), Bh[16K,24K)
#define STAGE 24576
#define GEMM_SMEM (2 * STAGE)

__device__ __forceinline__ void issue_tile(int kc, uint32_t sst, int tid, int m0, int n0)
{
    int k0 = kc * 32;
    #pragma unroll
    for (int p = 0; p < 2; p++) {
        int id = tid + p * 256;               // 0..511
        int kr = id >> 4, cm = id & 15;
        uint32_t so = (uint32_t)((cm >> 3) * 4096) + SW128((uint32_t)(kr * 128 + (cm & 7) * 16));
        const __half* gh = g_colh + (size_t)(k0 + kr) * Mpix + m0 + cm * 8;
        const __half* gl = g_coll + (size_t)(k0 + kr) * Mpix + m0 + cm * 8;
        cpasync16(sst + so, gh);
        cpasync16(sst + 8192 + so, gl);
    }
    #pragma unroll
    for (int p = 0; p < 2; p++) {
        int id = tid + p * 256;               // 0..511
        int o = id >> 2, cc = id & 3;
        uint32_t so = (uint32_t)(o * 64 + ((cc ^ ((o >> 1) & 3)) << 4));
        const __half* gh = g_Bh + (size_t)kc * (Pp * 32) + (n0 + o) * 32 + cc * 8;
        cpasync16(sst + 16384 + so, gh);
    }
}

__global__ __launch_bounds__(256, 2) void k_gemm_mma()
{
    extern __shared__ char smem[];
    uint32_t sb = smem_u32(smem);
    int tid = threadIdx.x;
    int lane = tid & 31, wid = tid >> 5;
    int wm = wid & 1, wn = wid >> 1;
    int m0 = blockIdx.x * 128;
    int n0 = blockIdx.y * 128;

    int q = lane >> 3, r = lane & 7;
    int kb = (q >> 1) * 8, mb = (q & 1) * 8;
    int aoff[4];
    #pragma unroll
    for (int fm = 0; fm < 4; fm++) {
        int m = wm * 64 + fm * 16 + mb;
        int half = m >> 6, ml = m & 63, c = ml >> 3;
        aoff[fm] = half * 4096 + (kb + r) * 128 + ((c ^ r) << 4);
    }
    int bno[2], bsw[2];
    int cq = q & 1;
    #pragma unroll
    for (int g = 0; g < 2; g++) {
        int n = wn * 32 + g * 16 + ((q >> 1) & 1) * 8 + r;
        bno[g] = n * 64;
        bsw[g] = (n >> 1) & 3;
    }

    float acc[4][4][4];
    #pragma unroll
    for (int fm = 0; fm < 4; fm++)
        #pragma unroll
        for (int fn = 0; fn < 4; fn++)
            #pragma unroll
            for (int i = 0; i < 4; i++) acc[fm][fn][i] = 0.f;

    issue_tile(0, sb, tid, m0, n0);
    cp_commit();

    for (int it = 0; it < NIT; it++) {
        if (it + 1 < NIT) {
            issue_tile(it + 1, sb + ((it + 1) & 1) * STAGE, tid, m0, n0);
            cp_commit();
            cp_wait<1>();
        } else {
            cp_wait<0>();
        }
        __syncthreads();

        uint32_t abase = sb + (it & 1) * STAGE;
        uint32_t bbase = abase + 16384;

        #pragma unroll
        for (int ks = 0; ks < 2; ks++) {
            uint32_t ah[4][4], al[4][4], bq[2][4];
            #pragma unroll
            for (int fm = 0; fm < 4; fm++)
                ldsm4t(ah[fm], abase + aoff[fm] + ks * 2048);
            #pragma unroll
            for (int fm = 0; fm < 4; fm++)
                ldsm4t(al[fm], abase + 8192 + aoff[fm] + ks * 2048);
            #pragma unroll
            for (int g = 0; g < 2; g++)
                ldsm4(bq[g], bbase + bno[g] + (((ks * 2 + cq) ^ bsw[g]) << 4));
            #pragma unroll
            for (int g = 0; g < 2; g++)
                #pragma unroll
                for (int h = 0; h < 2; h++)
                    #pragma unroll
                    for (int fm = 0; fm < 4; fm++) {
                        mma16816(acc[fm][g * 2 + h], ah[fm], &bq[g][h * 2]);
                        mma16816(acc[fm][g * 2 + h], al[fm], &bq[g][h * 2]);
                    }
        }
        __syncthreads();
    }

    int mrow = m0 + wm * 64 + (lane >> 2);
    int ocol = n0 + wn * 32 + (lane & 3) * 2;
    #pragma unroll
    for (int fm = 0; fm < 4; fm++) {
        int m = mrow + fm * 16;
        #pragma unroll
        for (int fn = 0; fn < 4; fn++) {
            int o = ocol + fn * 8;
            *(float2*)&g_y[(size_t)m * Pp + o]       = make_float2(acc[fm][fn][0], acc[fm][fn][1]);
            *(float2*)&g_y[(size_t)(m + 8) * Pp + o] = make_float2(acc[fm][fn][2], acc[fm][fn][3]);
        }
    }
}

// ---------------- kernel 7: BN partial stats ----------------
__global__ __launch_bounds__(256) void k_bnstats()
{
    int bb = blockIdx.x, t = threadIdx.x;
    float s = 0.f, s2 = 0.f;
    const float* yr = g_y + (size_t)bb * 128 * Pp + t;
    for (int i = 0; i < 128; i++) {
        float v = yr[(size_t)i * Pp];
        s += v;
        s2 = fmaf(v, v, s2);
    }
    g_psum[bb * Pp + t] = s;
    g_psum2[bb * Pp + t] = s2;
}

// ---------------- kernel 8: BN finalize ----------------
__global__ __launch_bounds__(256) void k_bnfin(
    const float* __restrict__ gamma, const float* __restrict__ beta)
{
    int o = threadIdx.x;
    float s = 0.f, s2 = 0.f;
    for (int b = 0; b < 128; b++) {
        s += g_psum[b * Pp + o];
        s2 += g_psum2[b * Pp + o];
    }
    float mean = s * (1.f / (float)Mpix);
    float var = s2 * (1.f / (float)Mpix) - mean * mean;
    float sc = gamma[o] * rsqrtf(var + 1e-5f);
    g_scale[o] = sc;
    g_shift[o] = beta[o] - mean * sc;
}

// ---------------- kernel 9: BN apply + ReLU ----------------
__global__ __launch_bounds__(256) void k_bnapply(float* __restrict__ out)
{
    __shared__ float st[256][36];
    __shared__ float sc[256], sh[256];
    int t = threadIdx.x;
    int m0 = blockIdx.x * 32;
    sc[t] = g_scale[t];
    sh[t] = g_shift[t];
    __syncthreads();

    #pragma unroll
    for (int p = 0; p < 8; p++) {
        int idx = t + p * 256;
        int mi = idx >> 6, oc4 = idx & 63;
        float4 v = *(const float4*)&g_y[(size_t)(m0 + mi) * Pp + oc4 * 4];
        int o = oc4 * 4;
        st[o + 0][mi] = fmaxf(fmaf(v.x, sc[o + 0], sh[o + 0]), 0.f);
        st[o + 1][mi] = fmaxf(fmaf(v.y, sc[o + 1], sh[o + 1]), 0.f);
        st[o + 2][mi] = fmaxf(fmaf(v.z, sc[o + 2], sh[o + 2]), 0.f);
        st[o + 3][mi] = fmaxf(fmaf(v.w, sc[o + 3], sh[o + 3]), 0.f);
    }
    __syncthreads();

    int b = m0 >> 12;
    int hw0 = m0 & 4095;
    #pragma unroll
    for (int p = 0; p < 8; p++) {
        int idx = t + p * 256;
        int o = idx >> 3, mq = idx & 7;
        float4 v = *(const float4*)&st[o][mq * 4];
        *(float4*)&out[(size_t)(b * 256 + o) * 4096 + hw0 + mq * 4] = v;
    }
}

// ---------------- launch ----------------
extern "C" void kernel_launch(void* const* d_in, const int* in_sizes, int n_in,
                              void* d_out, int out_size)
{
    const float* x     = (const float*)d_in[0];
    const float* w_p   = (const float*)d_in[1];
    const float* b_p   = (const float*)d_in[2];
    const float* w_m   = (const float*)d_in[3];
    const float* b_m   = (const float*)d_in[4];
    const float* w     = (const float*)d_in[5];
    const float* gamma = (const float*)d_in[6];
    const float* beta  = (const float*)d_in[7];
    float* out = (float*)d_out;

    cudaFuncSetAttribute(k_gemm_mma, cudaFuncAttributeMaxDynamicSharedMemorySize, GEMM_SMEM);

    k_xsplit<<<dim3(128, 8, Bn), dim3(32, 8)>>>(x);
    k_wcpack<<<288, 256>>>(w_p, w_m);
    k_convmma<<<Mpix / 128, 256>>>(b_p, b_m);
    k_sample<<<dim3(Hh, NK, Bn), dim3(32, 8)>>>(x);
    k_wpack<<<(Pp * Kdim + 255) / 256, 256>>>(w);
    k_gemm_mma<<<dim3(Mpix / 128, 2), 256, GEMM_SMEM>>>();
    k_bnstats<<<128, 256>>>();
    k_bnfin<<<1, 256>>>(gamma, beta);
    k_bnapply<<<Mpix / 32, 256>>>(out);
}

// round 11
// speedup vs baseline: 4.6677x; 1.0818x over previous
#include <cuda_runtime.h>
#include <cuda_fp16.h>
#include <math.h>
#include <stdint.h>

// Problem constants
#define Bn   4
#define Cc   256
#define Hh   64
#define Ww   64
#define Pp   256
#define NK   9
#define PADc 6
#define DILc 6
#define Hp   76
#define Wp   76
#define Mpix (Bn*Hh*Ww)     // 16384
#define Kdim (Cc*NK)        // 2304
#define NIT  (Kdim/32)      // 72

// ---------------- scratch ----------------
__device__ float  g_offmask[Bn * 27 * Hh * Ww];                  // [b][ch0..26][h][w]
__device__ __half g_xh[(size_t)Mpix * Cc];                       // xT hi [m][c]
__device__ __half g_xl[(size_t)Mpix * Cc];                       // xT lo
__device__ __half g_Wch[72 * 32 * 32];                           // conv W hi [it][o][c32]
__device__ __half g_colh[(size_t)Mpix * Kdim];                   // A hi [m][k], k = kk*256+c
__device__ __half g_coll[(size_t)Mpix * Kdim];                   // A lo [m][k]
__device__ __half g_Bh[(size_t)NIT * Pp * 32];                   // B hi [kc][o][32], new k order
__device__ float  g_y[(size_t)Mpix * Pp];                        // y[m][o]
__device__ float  g_psum[128 * Pp];
__device__ float  g_psum2[128 * Pp];
__device__ float  g_scale[Pp];
__device__ float  g_shift[Pp];

#define SW128(off) ((off) ^ (((off) >> 3) & 0x70))

// ---------------- ptx helpers ----------------
__device__ __forceinline__ uint32_t smem_u32(const void* p) {
    uint32_t a;
    asm("{ .reg .u64 t; cvta.to.shared.u64 t, %1; cvt.u32.u64 %0, t; }" : "=r"(a) : "l"(p));
    return a;
}
__device__ __forceinline__ void cpasync16(uint32_t s, const void* g) {
    asm volatile("cp.async.cg.shared.global [%0], [%1], 16;" :: "r"(s), "l"(g));
}
__device__ __forceinline__ void cpasync16z(uint32_t s, const void* g, uint32_t srcsz) {
    asm volatile("cp.async.cg.shared.global [%0], [%1], 16, %2;" :: "r"(s), "l"(g), "r"(srcsz));
}
__device__ __forceinline__ void cp_commit() {
    asm volatile("cp.async.commit_group;" ::: "memory");
}
template <int N> __device__ __forceinline__ void cp_wait() {
    asm volatile("cp.async.wait_group %0;" :: "n"(N) : "memory");
}
__device__ __forceinline__ void ldsm4(uint32_t* r, uint32_t a) {
    asm volatile("ldmatrix.sync.aligned.m8n8.x4.shared.b16 {%0,%1,%2,%3}, [%4];"
                 : "=r"(r[0]), "=r"(r[1]), "=r"(r[2]), "=r"(r[3]) : "r"(a));
}
__device__ __forceinline__ void mma16816(float* c, const uint32_t* a, const uint32_t* b) {
    asm volatile("mma.sync.aligned.m16n8k16.row.col.f32.f16.f16.f32 "
                 "{%0,%1,%2,%3}, {%4,%5,%6,%7}, {%8,%9}, {%0,%1,%2,%3};"
                 : "+f"(c[0]), "+f"(c[1]), "+f"(c[2]), "+f"(c[3])
                 : "r"(a[0]), "r"(a[1]), "r"(a[2]), "r"(a[3]), "r"(b[0]), "r"(b[1]));
}

// ---------------- kernel 1: x transpose + fp16 split ----------------
__global__ __launch_bounds__(256) void k_xsplit(const float* __restrict__ x)
{
    __shared__ float t[32][33];
    int hw0 = blockIdx.x * 32;
    int c0  = blockIdx.y * 32;
    int b   = blockIdx.z;
    int tx = threadIdx.x, ty = threadIdx.y;

    #pragma unroll
    for (int p = 0; p < 4; p++)
        t[ty + 8 * p][tx] = x[(size_t)(b * 256 + c0 + ty + 8 * p) * 4096 + hw0 + tx];
    __syncthreads();
    #pragma unroll
    for (int p = 0; p < 4; p++) {
        float v = t[tx][ty + 8 * p];
        __half hi = __float2half_rn(v);
        float lo = v - __half2float(hi);
        size_t idx = (size_t)(b * 4096 + hw0 + ty + 8 * p) * 256 + c0 + tx;
        g_xh[idx] = hi;
        g_xl[idx] = __float2half_rn(lo);
    }
}

// ---------------- kernel 2: conv weight pack (hi only) ----------------
__global__ __launch_bounds__(256) void k_wcpack(
    const float* __restrict__ w_p, const float* __restrict__ w_m)
{
    int i = blockIdx.x * 256 + threadIdx.x;     // 0..73727
    int it = i >> 10, o = (i >> 5) & 31, ci = i & 31;
    int j = it >> 3, cc = it & 7;
    int c = cc * 32 + ci;
    float v = 0.f;
    if (o < 18)      v = w_p[(size_t)o * Kdim + c * 9 + j];
    else if (o < 27) v = w_m[(size_t)(o - 18) * Kdim + c * 9 + j];
    g_Wch[i] = __float2half_rn(v);
}

// ---------------- kernel 3: offset+mask conv as HMMA GEMM (2-pass) ----------------
#define CSTAGE 18432
__global__ __launch_bounds__(256, 2) void k_convmma(
    const float* __restrict__ b_p, const float* __restrict__ b_m)
{
    __shared__ char csm[2][CSTAGE];
    __shared__ float sbias[32];
    uint32_t sb0 = smem_u32(&csm[0][0]);
    int tid = threadIdx.x;
    int lane = tid & 31, wid = tid >> 5;
    int m0 = blockIdx.x * 128;

    if (tid < 32) sbias[tid] = (tid < 18) ? b_p[tid] : (tid < 27 ? b_m[tid - 18] : 0.f);

    int q = lane >> 3, r = lane & 7;
    int arow = wid * 16 + r + (q & 1) * 8;
    int acix = q >> 1;
    uint32_t aso_base = (uint32_t)(arow * 64);
    int arsw = (arow >> 1) & 3;

    int bn[2], bsw[2];
    int cq = q & 1;
    #pragma unroll
    for (int g = 0; g < 2; g++) {
        int n = g * 16 + ((q >> 1) & 1) * 8 + r;
        bn[g] = n * 64;
        bsw[g] = (n >> 1) & 3;
    }

    float acc[4][4];
    #pragma unroll
    for (int fn = 0; fn < 4; fn++)
        #pragma unroll
        for (int i = 0; i < 4; i++) acc[fn][i] = 0.f;

    auto issue = [&](int it, int buf) {
        uint32_t sst = sb0 + buf * CSTAGE;
        int j = it >> 3, cc = it & 7;
        int dh = j / 3 - 1, dw = j % 3 - 1;
        int delta = dh * 64 + dw;
        int c0 = cc * 32;
        #pragma unroll
        for (int p = 0; p < 4; p++) {
            int id = tid + p * 256;
            int row = id >> 3, sub = id & 7;
            int half = sub >> 2, ci = sub & 3;
            int h = ((m0 + row) >> 6) & 63, w = row & 63;
            bool valid = ((unsigned)(h + dh) < 64u) && ((unsigned)(w + dw) < 64u);
            const __half* src = (half ? g_xl : g_xh);
            const __half* gp = valid ? (src + (size_t)(m0 + row + delta) * 256 + c0 + ci * 8)
                                     : src;
            uint32_t dst = sst + half * 8192 + row * 64 + ((ci ^ ((row >> 1) & 3)) << 4);
            cpasync16z(dst, gp, valid ? 16u : 0u);
        }
        if (tid < 128) {
            int o = tid >> 2, ci = tid & 3;
            const __half* gp = g_Wch + ((size_t)it * 32 + o) * 32 + ci * 8;
            uint32_t dst = sst + 16384 + o * 64 + ((ci ^ ((o >> 1) & 3)) << 4);
            cpasync16(dst, gp);
        }
    };

    issue(0, 0);
    cp_commit();

    for (int it = 0; it < 72; it++) {
        if (it + 1 < 72) {
            issue(it + 1, (it + 1) & 1);
            cp_commit();
            cp_wait<1>();
        } else {
            cp_wait<0>();
        }
        __syncthreads();

        uint32_t abase = sb0 + (it & 1) * CSTAGE;
        uint32_t bbase = abase + 16384;

        #pragma unroll
        for (int ks = 0; ks < 2; ks++) {
            uint32_t ah[4], al[4], bq[2][4];
            {
                int ci = ks * 2 + acix;
                uint32_t so = aso_base + ((ci ^ arsw) << 4);
                ldsm4(ah, abase + so);
                ldsm4(al, abase + 8192 + so);
            }
            #pragma unroll
            for (int g = 0; g < 2; g++)
                ldsm4(bq[g], bbase + bn[g] + (((ks * 2 + cq) ^ bsw[g]) << 4));
            #pragma unroll
            for (int g = 0; g < 2; g++)
                #pragma unroll
                for (int h = 0; h < 2; h++) {
                    mma16816(acc[g * 2 + h], ah, &bq[g][h * 2]);
                    mma16816(acc[g * 2 + h], al, &bq[g][h * 2]);
                }
        }
        __syncthreads();
    }

    int mbase = m0 + wid * 16 + (lane >> 2);
    #pragma unroll
    for (int fn = 0; fn < 4; fn++) {
        #pragma unroll
        for (int hf = 0; hf < 2; hf++) {
            int m = mbase + hf * 8;
            int b = m >> 12, hw = m & 4095;
            #pragma unroll
            for (int e = 0; e < 2; e++) {
                int o = fn * 8 + (lane & 3) * 2 + e;
                if (o < 27)
                    g_offmask[(size_t)(b * 27 + o) * 4096 + hw] = acc[fn][hf * 2 + e] + sbias[o];
            }
        }
    }
}

// ---------------- kernel 4: coalesced deformable sampling ----------------
// warp per (m, kk): 4 tap rows of 256 contiguous channels in g_xh/g_xl,
// writes A[m][kk*256 .. +256] hi/lo contiguous. 8 warps/block.
__global__ __launch_bounds__(256) void k_sample2()
{
    int wid = threadIdx.x >> 5, lane = threadIdx.x & 31;
    int id = blockIdx.x * 8 + wid;            // 0..147455
    int m = id / 9, kk = id - m * 9;
    int b = m >> 12, hw = m & 4095;
    int h = hw >> 6, w = hw & 63;

    float offx = g_offmask[(size_t)(b * 27 + kk) * 4096 + hw];
    float offy = g_offmask[(size_t)(b * 27 + 9 + kk) * 4096 + hw];
    float mlog = g_offmask[(size_t)(b * 27 + 18 + kk) * 4096 + hw];
    float mask = 1.f / (1.f + expf(-mlog));

    int knh = kk / 3, knw = kk % 3;
    float px = (float)(h + 1) + (float)((knh - 1) * DILc) + offx;
    float py = (float)(w + 1) + (float)((knw - 1) * DILc) + offy;

    float flx = floorf(px), fly = floorf(py);
    float qltx = fminf(fmaxf(flx,       0.f), (float)(Hp - 1));
    float qlty = fminf(fmaxf(fly,       0.f), (float)(Wp - 1));
    float qrbx = fminf(fmaxf(flx + 1.f, 0.f), (float)(Hp - 1));
    float qrby = fminf(fmaxf(fly + 1.f, 0.f), (float)(Wp - 1));
    float pxc  = fminf(fmaxf(px, 0.f), (float)(Hp - 1));
    float pyc  = fminf(fmaxf(py, 0.f), (float)(Wp - 1));

    float glt = (1.f + (qltx - pxc)) * (1.f + (qlty - pyc)) * mask;
    float grb = (1.f - (qrbx - pxc)) * (1.f - (qrby - pyc)) * mask;
    float glb = (1.f + (qltx - pxc)) * (1.f - (qrby - pyc)) * mask;
    float grt = (1.f - (qrbx - pxc)) * (1.f + (qlty - pyc)) * mask;

    int ltx = (int)qltx - PADc, lty = (int)qlty - PADc;
    int rbx = (int)qrbx - PADc, rby = (int)qrby - PADc;
    bool vltx = (unsigned)ltx < (unsigned)Hh, vlty = (unsigned)lty < (unsigned)Ww;
    bool vrbx = (unsigned)rbx < (unsigned)Hh, vrby = (unsigned)rby < (unsigned)Ww;

    bool bLT = vltx && vlty, bRB = vrbx && vrby;
    bool bLB = vltx && vrby, bRT = vrbx && vlty;

    float  wgt[4];
    size_t tap[4];
    int mb = b * 4096;
    wgt[0] = bLT ? glt : 0.f;  tap[0] = (size_t)(mb + (bLT ? (ltx * Ww + lty) : 0)) * 256;
    wgt[1] = bRB ? grb : 0.f;  tap[1] = (size_t)(mb + (bRB ? (rbx * Ww + rby) : 0)) * 256;
    wgt[2] = bLB ? glb : 0.f;  tap[2] = (size_t)(mb + (bLB ? (ltx * Ww + rby) : 0)) * 256;
    wgt[3] = bRT ? grt : 0.f;  tap[3] = (size_t)(mb + (bRT ? (rbx * Ww + lty) : 0)) * 256;

    size_t obase = (size_t)m * Kdim + kk * 256;

    #pragma unroll
    for (int step = 0; step < 2; step++) {
        int c = (step * 32 + lane) * 4;       // 4 channels per lane
        float2 v01 = make_float2(0.f, 0.f);
        float2 v23 = make_float2(0.f, 0.f);
        #pragma unroll
        for (int t = 0; t < 4; t++) {
            uint2 hh = *(const uint2*)(g_xh + tap[t] + c);
            uint2 ll = *(const uint2*)(g_xl + tap[t] + c);
            float2 h01 = __half22float2(*(__half2*)&hh.x);
            float2 h23 = __half22float2(*(__half2*)&hh.y);
            float2 l01 = __half22float2(*(__half2*)&ll.x);
            float2 l23 = __half22float2(*(__half2*)&ll.y);
            v01.x = fmaf(wgt[t], h01.x + l01.x, v01.x);
            v01.y = fmaf(wgt[t], h01.y + l01.y, v01.y);
            v23.x = fmaf(wgt[t], h23.x + l23.x, v23.x);
            v23.y = fmaf(wgt[t], h23.y + l23.y, v23.y);
        }
        __half h0 = __float2half_rn(v01.x), h1 = __float2half_rn(v01.y);
        __half h2 = __float2half_rn(v23.x), h3 = __float2half_rn(v23.y);
        __half l0 = __float2half_rn(v01.x - __half2float(h0));
        __half l1 = __float2half_rn(v01.y - __half2float(h1));
        __half l2 = __float2half_rn(v23.x - __half2float(h2));
        __half l3 = __float2half_rn(v23.y - __half2float(h3));
        uint2 oh, ol;
        *(__half2*)&oh.x = __halves2half2(h0, h1);
        *(__half2*)&oh.y = __halves2half2(h2, h3);
        *(__half2*)&ol.x = __halves2half2(l0, l1);
        *(__half2*)&ol.y = __halves2half2(l2, l3);
        *(uint2*)&g_colh[obase + c] = oh;
        *(uint2*)&g_coll[obase + c] = ol;
    }
}

// ---------------- kernel 5: main weight pack (hi only, kk-major k order) ----------------
__global__ __launch_bounds__(256) void k_wpack(const float* __restrict__ w)
{
    int i = blockIdx.x * 256 + threadIdx.x;
    if (i < Pp * Kdim) {
        int o = i / Kdim, kold = i % Kdim;    // kold = c*9 + kk
        int c = kold / 9, kk = kold - c * 9;
        int kn = kk * 256 + c;
        size_t idx = (size_t)(kn >> 5) * (Pp * 32) + o * 32 + (kn & 31);
        g_Bh[idx] = __float2half_rn(w[i]);
    }
}

// ---------------- kernel 6: main HMMA GEMM 128x128 tiles, 2-pass, A m-major ----------------
// stage 24 KB: Ah[0,8K) (128m x 64B rows), Al[8K,16K), Bh[16K,24K)
#define STAGE 24576
#define GEMM_SMEM (2 * STAGE)

__device__ __forceinline__ void issue_tile(int kc, uint32_t sst, int tid, int m0, int n0)
{
    int k0 = kc * 32;
    #pragma unroll
    for (int p = 0; p < 2; p++) {
        int id = tid + p * 256;               // 0..511
        int row = id >> 2, ci = id & 3;
        size_t gofs = ((size_t)(m0 + row) * Kdim + k0) * 2 + ci * 16;
        uint32_t so = (uint32_t)(row * 64 + ((ci ^ ((row >> 1) & 3)) << 4));
        cpasync16(sst + so, (const char*)g_colh + gofs);
        cpasync16(sst + 8192 + so, (const char*)g_coll + gofs);
    }
    #pragma unroll
    for (int p = 0; p < 2; p++) {
        int id = tid + p * 256;               // 0..511
        int o = id >> 2, cc = id & 3;
        uint32_t so = (uint32_t)(o * 64 + ((cc ^ ((o >> 1) & 3)) << 4));
        const __half* gh = g_Bh + (size_t)kc * (Pp * 32) + (n0 + o) * 32 + cc * 8;
        cpasync16(sst + 16384 + so, gh);
    }
}

__global__ __launch_bounds__(256, 2) void k_gemm_mma()
{
    extern __shared__ char smem[];
    uint32_t sb = smem_u32(smem);
    int tid = threadIdx.x;
    int lane = tid & 31, wid = tid >> 5;
    int wm = wid & 1, wn = wid >> 1;
    int m0 = blockIdx.x * 128;
    int n0 = blockIdx.y * 128;

    int q = lane >> 3, r = lane & 7;
    int acix = q >> 1;
    uint32_t aoff[4];
    int asw[4];
    #pragma unroll
    for (int fm = 0; fm < 4; fm++) {
        int row = wm * 64 + fm * 16 + (q & 1) * 8 + r;
        aoff[fm] = (uint32_t)(row * 64);
        asw[fm] = (row >> 1) & 3;
    }
    int bno[2], bsw[2];
    int cq = q & 1;
    #pragma unroll
    for (int g = 0; g < 2; g++) {
        int n = wn * 32 + g * 16 + ((q >> 1) & 1) * 8 + r;
        bno[g] = n * 64;
        bsw[g] = (n >> 1) & 3;
    }

    float acc[4][4][4];
    #pragma unroll
    for (int fm = 0; fm < 4; fm++)
        #pragma unroll
        for (int fn = 0; fn < 4; fn++)
            #pragma unroll
            for (int i = 0; i < 4; i++) acc[fm][fn][i] = 0.f;

    issue_tile(0, sb, tid, m0, n0);
    cp_commit();

    for (int it = 0; it < NIT; it++) {
        if (it + 1 < NIT) {
            issue_tile(it + 1, sb + ((it + 1) & 1) * STAGE, tid, m0, n0);
            cp_commit();
            cp_wait<1>();
        } else {
            cp_wait<0>();
        }
        __syncthreads();

        uint32_t abase = sb + (it & 1) * STAGE;
        uint32_t bbase = abase + 16384;

        #pragma unroll
        for (int ks = 0; ks < 2; ks++) {
            uint32_t ah[4][4], al[4][4], bq[2][4];
            #pragma unroll
            for (int fm = 0; fm < 4; fm++) {
                int ci = ks * 2 + acix;
                uint32_t so = aoff[fm] + ((ci ^ asw[fm]) << 4);
                ldsm4(ah[fm], abase + so);
                ldsm4(al[fm], abase + 8192 + so);
            }
            #pragma unroll
            for (int g = 0; g < 2; g++)
                ldsm4(bq[g], bbase + bno[g] + (((ks * 2 + cq) ^ bsw[g]) << 4));
            #pragma unroll
            for (int g = 0; g < 2; g++)
                #pragma unroll
                for (int h = 0; h < 2; h++)
                    #pragma unroll
                    for (int fm = 0; fm < 4; fm++) {
                        mma16816(acc[fm][g * 2 + h], ah[fm], &bq[g][h * 2]);
                        mma16816(acc[fm][g * 2 + h], al[fm], &bq[g][h * 2]);
                    }
        }
        __syncthreads();
    }

    int mrow = m0 + wm * 64 + (lane >> 2);
    int ocol = n0 + wn * 32 + (lane & 3) * 2;
    #pragma unroll
    for (int fm = 0; fm < 4; fm++) {
        int m = mrow + fm * 16;
        #pragma unroll
        for (int fn = 0; fn < 4; fn++) {
            int o = ocol + fn * 8;
            *(float2*)&g_y[(size_t)m * Pp + o]       = make_float2(acc[fm][fn][0], acc[fm][fn][1]);
            *(float2*)&g_y[(size_t)(m + 8) * Pp + o] = make_float2(acc[fm][fn][2], acc[fm][fn][3]);
        }
    }
}

// ---------------- kernel 7: BN partial stats ----------------
__global__ __launch_bounds__(256) void k_bnstats()
{
    int bb = blockIdx.x, t = threadIdx.x;
    float s = 0.f, s2 = 0.f;
    const float* yr = g_y + (size_t)bb * 128 * Pp + t;
    for (int i = 0; i < 128; i++) {
        float v = yr[(size_t)i * Pp];
        s += v;
        s2 = fmaf(v, v, s2);
    }
    g_psum[bb * Pp + t] = s;
    g_psum2[bb * Pp + t] = s2;
}

// ---------------- kernel 8: BN finalize ----------------
__global__ __launch_bounds__(256) void k_bnfin(
    const float* __restrict__ gamma, const float* __restrict__ beta)
{
    int o = threadIdx.x;
    float s = 0.f, s2 = 0.f;
    for (int b = 0; b < 128; b++) {
        s += g_psum[b * Pp + o];
        s2 += g_psum2[b * Pp + o];
    }
    float mean = s * (1.f / (float)Mpix);
    float var = s2 * (1.f / (float)Mpix) - mean * mean;
    float sc = gamma[o] * rsqrtf(var + 1e-5f);
    g_scale[o] = sc;
    g_shift[o] = beta[o] - mean * sc;
}

// ---------------- kernel 9: BN apply + ReLU ----------------
__global__ __launch_bounds__(256) void k_bnapply(float* __restrict__ out)
{
    __shared__ float st[256][36];
    __shared__ float sc[256], sh[256];
    int t = threadIdx.x;
    int m0 = blockIdx.x * 32;
    sc[t] = g_scale[t];
    sh[t] = g_shift[t];
    __syncthreads();

    #pragma unroll
    for (int p = 0; p < 8; p++) {
        int idx = t + p * 256;
        int mi = idx >> 6, oc4 = idx & 63;
        float4 v = *(const float4*)&g_y[(size_t)(m0 + mi) * Pp + oc4 * 4];
        int o = oc4 * 4;
        st[o + 0][mi] = fmaxf(fmaf(v.x, sc[o + 0], sh[o + 0]), 0.f);
        st[o + 1][mi] = fmaxf(fmaf(v.y, sc[o + 1], sh[o + 1]), 0.f);
        st[o + 2][mi] = fmaxf(fmaf(v.z, sc[o + 2], sh[o + 2]), 0.f);
        st[o + 3][mi] = fmaxf(fmaf(v.w, sc[o + 3], sh[o + 3]), 0.f);
    }
    __syncthreads();

    int b = m0 >> 12;
    int hw0 = m0 & 4095;
    #pragma unroll
    for (int p = 0; p < 8; p++) {
        int idx = t + p * 256;
        int o = idx >> 3, mq = idx & 7;
        float4 v = *(const float4*)&st[o][mq * 4];
        *(float4*)&out[(size_t)(b * 256 + o) * 4096 + hw0 + mq * 4] = v;
    }
}

// ---------------- launch ----------------
extern "C" void kernel_launch(void* const* d_in, const int* in_sizes, int n_in,
                              void* d_out, int out_size)
{
    const float* x     = (const float*)d_in[0];
    const float* w_p   = (const float*)d_in[1];
    const float* b_p   = (const float*)d_in[2];
    const float* w_m   = (const float*)d_in[3];
    const float* b_m   = (const float*)d_in[4];
    const float* w     = (const float*)d_in[5];
    const float* gamma = (const float*)d_in[6];
    const float* beta  = (const float*)d_in[7];
    float* out = (float*)d_out;

    cudaFuncSetAttribute(k_gemm_mma, cudaFuncAttributeMaxDynamicSharedMemorySize, GEMM_SMEM);

    k_xsplit<<<dim3(128, 8, Bn), dim3(32, 8)>>>(x);
    k_wcpack<<<288, 256>>>(w_p, w_m);
    k_convmma<<<Mpix / 128, 256>>>(b_p, b_m);
    k_sample2<<<Mpix * 9 / 8, 256>>>();
    k_wpack<<<(Pp * Kdim + 255) / 256, 256>>>(w);
    k_gemm_mma<<<dim3(Mpix / 128, 2), 256, GEMM_SMEM>>>();
    k_bnstats<<<128, 256>>>();
    k_bnfin<<<1, 256>>>(gamma, beta);
    k_bnapply<<<Mpix / 32, 256>>>(out);
}